// round 3
// baseline (speedup 1.0000x reference)
#include <cuda_runtime.h>
#include <mma.h>
#include <math.h>

using namespace nvcuda;

#define BB 4
#define ND 512
#define NT 512
#define DM 256
#define NH 8
#define DK 32

// ---- scratch (static device globals; no runtime allocation) ----
__device__ float g_Q[BB*NH*ND*DK];        // [b,h,n,dk]
__device__ float g_K[BB*NH*NT*DK];        // [b,h,t,dk]
__device__ float g_V[BB*NH*NT*DK];        // [b,h,t,dk]
__device__ float g_ctx[BB*ND*DM];         // [b,n, h*32+dk]
__device__ float g_attout[BB*ND*DM];      // attended (pre-residual)
__device__ float g_xn[BB*ND*DM];          // LayerNorm output

// ============================================================
// QKV GEMM (merged): C[2048,256] = X @ W^T + bias, z selects Q/K/V
// ============================================================
__global__ void qkv_gemm(const float* __restrict__ det,
                         const float* __restrict__ trk,
                         const float* __restrict__ w_q, const float* __restrict__ b_q,
                         const float* __restrict__ w_k, const float* __restrict__ b_k,
                         const float* __restrict__ w_v, const float* __restrict__ b_v)
{
    int z = blockIdx.z;
    const float* X    = (z == 0) ? det : trk;
    const float* W    = (z == 0) ? w_q : (z == 1) ? w_k : w_v;
    const float* bias = (z == 0) ? b_q : (z == 1) ? b_k : b_v;
    float* O          = (z == 0) ? g_Q : (z == 1) ? g_K : g_V;

    __shared__ float Xs[16][65];
    __shared__ float Ws[16][65];
    int tid = threadIdx.x;
    int tx = tid & 15, ty = tid >> 4;
    int m0 = blockIdx.y * 64, n0 = blockIdx.x * 64;

    float acc[4][4] = {};
    for (int k0 = 0; k0 < 256; k0 += 16) {
        #pragma unroll
        for (int r = 0; r < 4; r++) {
            int idx = tid + 256 * r;
            int kk = idx & 15, mm = idx >> 4;
            Xs[kk][mm] = X[(m0 + mm) * 256 + k0 + kk];
            Ws[kk][mm] = W[(n0 + mm) * 256 + k0 + kk];
        }
        __syncthreads();
        #pragma unroll
        for (int kk = 0; kk < 16; kk++) {
            float a[4], b[4];
            #pragma unroll
            for (int i = 0; i < 4; i++) { a[i] = Xs[kk][ty*4+i]; b[i] = Ws[kk][tx*4+i]; }
            #pragma unroll
            for (int i = 0; i < 4; i++)
                #pragma unroll
                for (int j = 0; j < 4; j++)
                    acc[i][j] += a[i] * b[j];
        }
        __syncthreads();
    }
    #pragma unroll
    for (int i = 0; i < 4; i++) {
        int m = m0 + ty*4 + i;
        int b = m >> 9, nn = m & 511;
        #pragma unroll
        for (int j = 0; j < 4; j++) {
            int n = n0 + tx*4 + j;
            int h = n >> 5, dk = n & 31;
            O[((b * NH + h) * 512 + nn) * DK + dk] = acc[i][j] + bias[n];
        }
    }
}

// ============================================================
// output projection GEMM: g_attout = g_ctx @ w_o^T + b_o
// ============================================================
__global__ void gemm_o(const float* __restrict__ W, const float* __restrict__ bias)
{
    const float* X = g_ctx;
    __shared__ float Xs[16][65];
    __shared__ float Ws[16][65];
    int tid = threadIdx.x;
    int tx = tid & 15, ty = tid >> 4;
    int m0 = blockIdx.y * 64, n0 = blockIdx.x * 64;

    float acc[4][4] = {};
    for (int k0 = 0; k0 < 256; k0 += 16) {
        #pragma unroll
        for (int r = 0; r < 4; r++) {
            int idx = tid + 256 * r;
            int kk = idx & 15, mm = idx >> 4;
            Xs[kk][mm] = X[(m0 + mm) * 256 + k0 + kk];
            Ws[kk][mm] = W[(n0 + mm) * 256 + k0 + kk];
        }
        __syncthreads();
        #pragma unroll
        for (int kk = 0; kk < 16; kk++) {
            float a[4], b[4];
            #pragma unroll
            for (int i = 0; i < 4; i++) { a[i] = Xs[kk][ty*4+i]; b[i] = Ws[kk][tx*4+i]; }
            #pragma unroll
            for (int i = 0; i < 4; i++)
                #pragma unroll
                for (int j = 0; j < 4; j++)
                    acc[i][j] += a[i] * b[j];
        }
        __syncthreads();
    }
    #pragma unroll
    for (int i = 0; i < 4; i++) {
        int m = m0 + ty*4 + i;
        #pragma unroll
        for (int j = 0; j < 4; j++) {
            int n = n0 + tx*4 + j;
            g_attout[m * 256 + n] = acc[i][j] + bias[n];
        }
    }
}

// ============================================================
// Fused attention: per block (qtile 32, h, b)
// ============================================================
#define ATT_SMEM ((32*512 + 64*33 + 32*33) * 4)

__global__ void fused_attn()
{
    extern __shared__ float sm[];
    float* S  = sm;                        // [32][512]
    float* KV = sm + 32*512;               // [64][33]
    float* Qs = sm + 32*512 + 64*33;       // [32][33]

    int b = blockIdx.z, h = blockIdx.y, q0 = blockIdx.x * 32;
    int bh = b * NH + h;
    int tid = threadIdx.x;
    int warp = tid >> 5, lane = tid & 31;

    #pragma unroll
    for (int r = 0; r < 4; r++) {
        int idx = tid + 256 * r;
        int row = idx >> 5, d = idx & 31;
        Qs[row * 33 + d] = g_Q[(bh * ND + q0 + row) * DK + d];
    }

    const float scale = 0.17677669529663689f;

    for (int k0 = 0; k0 < NT; k0 += 64) {
        #pragma unroll
        for (int r = 0; r < 8; r++) {
            int idx = tid + 256 * r;
            int kk = idx >> 5, d = idx & 31;
            KV[kk * 33 + d] = g_K[(bh * NT + k0 + kk) * DK + d];
        }
        __syncthreads();
        float acc[4][2] = {};
        #pragma unroll
        for (int d = 0; d < 32; d++) {
            float kv0 = KV[lane * 33 + d];
            float kv1 = KV[(lane + 32) * 33 + d];
            #pragma unroll
            for (int qi = 0; qi < 4; qi++) {
                float qv = Qs[(warp * 4 + qi) * 33 + d];
                acc[qi][0] += qv * kv0;
                acc[qi][1] += qv * kv1;
            }
        }
        #pragma unroll
        for (int qi = 0; qi < 4; qi++) {
            S[(warp * 4 + qi) * 512 + k0 + lane]      = acc[qi][0] * scale;
            S[(warp * 4 + qi) * 512 + k0 + 32 + lane] = acc[qi][1] * scale;
        }
        __syncthreads();
    }

    #pragma unroll
    for (int qi = 0; qi < 4; qi++) {
        float* row = &S[(warp * 4 + qi) * 512];
        float v[16];
        float m = -1e30f;
        #pragma unroll
        for (int i = 0; i < 16; i++) { v[i] = row[i * 32 + lane]; m = fmaxf(m, v[i]); }
        #pragma unroll
        for (int o = 16; o; o >>= 1) m = fmaxf(m, __shfl_xor_sync(0xffffffffu, m, o));
        float sum = 0.f;
        #pragma unroll
        for (int i = 0; i < 16; i++) { v[i] = __expf(v[i] - m); sum += v[i]; }
        #pragma unroll
        for (int o = 16; o; o >>= 1) sum += __shfl_xor_sync(0xffffffffu, sum, o);
        float inv = 1.f / sum;
        #pragma unroll
        for (int i = 0; i < 16; i++) row[i * 32 + lane] = v[i] * inv;
    }

    float cacc[4] = {};
    for (int k0 = 0; k0 < NT; k0 += 64) {
        __syncthreads();
        #pragma unroll
        for (int r = 0; r < 8; r++) {
            int idx = tid + 256 * r;
            int kk = idx >> 5, d = idx & 31;
            KV[kk * 33 + d] = g_V[(bh * NT + k0 + kk) * DK + d];
        }
        __syncthreads();
        #pragma unroll
        for (int kk = 0; kk < 64; kk++) {
            float vv = KV[kk * 33 + lane];
            #pragma unroll
            for (int qi = 0; qi < 4; qi++)
                cacc[qi] += S[(warp * 4 + qi) * 512 + k0 + kk] * vv;
        }
    }
    #pragma unroll
    for (int qi = 0; qi < 4; qi++) {
        int q = q0 + warp * 4 + qi;
        g_ctx[(b * ND + q) * DM + h * DK + lane] = cacc[qi];
    }
}

// ============================================================
// residual + LayerNorm
// ============================================================
__global__ void ln_kernel(const float* __restrict__ det,
                          const float* __restrict__ ln_g,
                          const float* __restrict__ ln_b)
{
    int row = blockIdx.x, t = threadIdx.x;
    float x = det[row * 256 + t] + g_attout[row * 256 + t];
    float s1 = x, s2 = x * x;
    #pragma unroll
    for (int o = 16; o; o >>= 1) {
        s1 += __shfl_xor_sync(0xffffffffu, s1, o);
        s2 += __shfl_xor_sync(0xffffffffu, s2, o);
    }
    __shared__ float r1[8], r2[8];
    int w = t >> 5, l = t & 31;
    if (!l) { r1[w] = s1; r2[w] = s2; }
    __syncthreads();
    if (w == 0) {
        float a = (l < 8) ? r1[l] : 0.f;
        float c = (l < 8) ? r2[l] : 0.f;
        #pragma unroll
        for (int o = 4; o; o >>= 1) {
            a += __shfl_xor_sync(0xffffffffu, a, o);
            c += __shfl_xor_sync(0xffffffffu, c, o);
        }
        if (!l) { r1[0] = a; r2[0] = c; }
    }
    __syncthreads();
    float mu  = r1[0] * (1.f / 256.f);
    float var = r2[0] * (1.f / 256.f) - mu * mu;
    float xn = (x - mu) * rsqrtf(var + 1e-5f) * ln_g[t] + ln_b[t];
    g_xn[row * 256 + t] = xn;
}

// ============================================================
// Pairwise MLP v2: tracks-resident, n-loop, double-buffered B.
//   block = (t-tile 128, n-chunk of 8, b)
//   A[t,k] = tracks (tf32, resident);  B_n[h,k] = w1[h,k]*xn[n,k]
//   H = A @ B_n^T;  out = sigmoid(relu(H+b1)@w2 + b2)
// ============================================================
#define NPER 8
#define ALD 264    // 256 + 8 pad
#define BLD 40     // 32 + 8 pad
#define ELD 68     // 64 + 4 pad
#define AS_ELEMS (128*ALD)
#define MLP_SMEM ((AS_ELEMS + 2*128*BLD) * 4)

__global__ void __launch_bounds__(256, 1)
mlp_kernel(const float* __restrict__ tracks,
           const float* __restrict__ w1,
           const float* __restrict__ b1,
           const float* __restrict__ w2,
           const float* __restrict__ b2,
           float* __restrict__ out)
{
    extern __shared__ float sm[];
    float* As = sm;                           // [128][ALD] tf32 tracks
    float* Bs0 = sm + AS_ELEMS;               // [128][BLD]
    float* Bs1 = sm + AS_ELEMS + 128*BLD;     // [128][BLD]
    float* E  = sm + AS_ELEMS;                // epilogue overlay [128][ELD]
    __shared__ float xns[256];
    __shared__ float b1s[128], w2s[128];

    int b  = blockIdx.z;
    int t0 = blockIdx.x * 128;
    int n0 = blockIdx.y * NPER;
    int tid = threadIdx.x;
    int warp = tid >> 5, lane = tid & 31;
    int wt = (warp & 3) * 32;    // t offset
    int wh = (warp >> 2) * 64;   // h offset (0 or 64)

    if (tid < 128) { b1s[tid] = b1[tid]; w2s[tid] = w2[tid]; }
    float bias2 = b2[0];

    // stage tracks tile (tf32) once
    const float* trkb = tracks + ((size_t)(b * NT + t0)) * 256;
    #pragma unroll 8
    for (int t = 0; t < 128; t++)
        As[t * ALD + tid] = wmma::__float_to_tf32(trkb[t * 256 + tid]);

    int hrow = tid >> 5;        // 0..7 (h row base for staging)
    int kk   = tid & 31;

    for (int ni = 0; ni < NPER; ni++) {
        int n = n0 + ni;
        xns[tid] = g_xn[(b * ND + n) * DM + tid];

        wmma::fragment<wmma::accumulator, 16, 16, 8, float> cf[2][4];
        #pragma unroll
        for (int i = 0; i < 2; i++)
            #pragma unroll
            for (int j = 0; j < 4; j++) wmma::fill_fragment(cf[i][j], 0.f);

        __syncthreads();   // xns ready; E/Bs region free from prev epilogue

        // stage slab 0
        #pragma unroll
        for (int i = 0; i < 16; i++) {
            int h = hrow + i * 8;
            Bs0[h * BLD + kk] = wmma::__float_to_tf32(w1[h * 256 + kk] * xns[kk]);
        }
        __syncthreads();

        #pragma unroll
        for (int s = 0; s < 8; s++) {
            float* cur = (s & 1) ? Bs1 : Bs0;
            float* nxt = (s & 1) ? Bs0 : Bs1;
            if (s < 7) {
                int k0n = (s + 1) * 32;
                #pragma unroll
                for (int i = 0; i < 16; i++) {
                    int h = hrow + i * 8;
                    nxt[h * BLD + kk] =
                        wmma::__float_to_tf32(w1[h * 256 + k0n + kk] * xns[k0n + kk]);
                }
            }
            int k0 = s * 32;
            #pragma unroll
            for (int ks = 0; ks < 32; ks += 8) {
                wmma::fragment<wmma::matrix_a, 16, 16, 8, wmma::precision::tf32, wmma::row_major> af[2];
                wmma::fragment<wmma::matrix_b, 16, 16, 8, wmma::precision::tf32, wmma::col_major> bf[4];
                #pragma unroll
                for (int i = 0; i < 2; i++)
                    wmma::load_matrix_sync(af[i], &As[(wt + 16*i) * ALD + k0 + ks], ALD);
                #pragma unroll
                for (int j = 0; j < 4; j++)
                    wmma::load_matrix_sync(bf[j], &cur[(wh + 16*j) * BLD + ks], BLD);
                #pragma unroll
                for (int i = 0; i < 2; i++)
                    #pragma unroll
                    for (int j = 0; j < 4; j++)
                        wmma::mma_sync(cf[i][j], af[i], bf[j], cf[i][j]);
            }
            __syncthreads();
        }

        // ---- epilogue: two h-half passes through E (overlaid on Bs) ----
        float part[16];

        // pass 0: warps 0..3 hold h in [0,64)
        if (warp < 4) {
            #pragma unroll
            for (int i = 0; i < 2; i++)
                #pragma unroll
                for (int j = 0; j < 4; j++)
                    wmma::store_matrix_sync(&E[(wt + 16*i) * ELD + 16*j], cf[i][j],
                                            ELD, wmma::mem_row_major);
        }
        __syncthreads();
        #pragma unroll
        for (int r = 0; r < 16; r++) {
            int t = warp * 16 + r;
            float v0 = E[t * ELD + lane]      + b1s[lane];
            float v1 = E[t * ELD + 32 + lane] + b1s[32 + lane];
            part[r] = fmaxf(v0, 0.f) * w2s[lane] + fmaxf(v1, 0.f) * w2s[32 + lane];
        }
        __syncthreads();

        // pass 1: warps 4..7 hold h in [64,128)
        if (warp >= 4) {
            #pragma unroll
            for (int i = 0; i < 2; i++)
                #pragma unroll
                for (int j = 0; j < 4; j++)
                    wmma::store_matrix_sync(&E[(wt + 16*i) * ELD + 16*j], cf[i][j],
                                            ELD, wmma::mem_row_major);
        }
        __syncthreads();
        #pragma unroll
        for (int r = 0; r < 16; r++) {
            int t = warp * 16 + r;
            float v0 = E[t * ELD + lane]      + b1s[64 + lane];
            float v1 = E[t * ELD + 32 + lane] + b1s[96 + lane];
            part[r] += fmaxf(v0, 0.f) * w2s[64 + lane] + fmaxf(v1, 0.f) * w2s[96 + lane];
            #pragma unroll
            for (int o = 16; o; o >>= 1)
                part[r] += __shfl_xor_sync(0xffffffffu, part[r], o);
            if (lane == 0) {
                float logit = part[r] + bias2;
                out[((size_t)(b * ND + n)) * NT + t0 + warp * 16 + r] =
                    1.f / (1.f + __expf(-logit));
            }
        }
    }
}

// ============================================================
extern "C" void kernel_launch(void* const* d_in, const int* in_sizes, int n_in,
                              void* d_out, int out_size)
{
    const float* det  = (const float*)d_in[0];
    const float* trk  = (const float*)d_in[1];
    const float* w_q  = (const float*)d_in[2];
    const float* b_q  = (const float*)d_in[3];
    const float* w_k  = (const float*)d_in[4];
    const float* b_k  = (const float*)d_in[5];
    const float* w_v  = (const float*)d_in[6];
    const float* b_v  = (const float*)d_in[7];
    const float* w_o  = (const float*)d_in[8];
    const float* b_o  = (const float*)d_in[9];
    const float* ln_g = (const float*)d_in[10];
    const float* ln_b = (const float*)d_in[11];
    const float* w1   = (const float*)d_in[12];
    const float* b1   = (const float*)d_in[13];
    const float* w2   = (const float*)d_in[14];
    const float* b2   = (const float*)d_in[15];
    float* out = (float*)d_out;

    cudaFuncSetAttribute(mlp_kernel,
                         cudaFuncAttributeMaxDynamicSharedMemorySize, MLP_SMEM);
    cudaFuncSetAttribute(fused_attn,
                         cudaFuncAttributeMaxDynamicSharedMemorySize, ATT_SMEM);

    qkv_gemm<<<dim3(4, 32, 3), 256>>>(det, trk, w_q, b_q, w_k, b_k, w_v, b_v);
    fused_attn<<<dim3(16, NH, BB), 256, ATT_SMEM>>>();
    gemm_o<<<dim3(4, 32), 256>>>(w_o, b_o);
    ln_kernel<<<BB * ND, 256>>>(det, ln_g, ln_b);
    mlp_kernel<<<dim3(4, 64, BB), 256, MLP_SMEM>>>(trk, w1, b1, w2, b2, out);
}

// round 5
// speedup vs baseline: 2.9270x; 2.9270x over previous
#include <cuda_runtime.h>
#include <cuda_fp16.h>
#include <mma.h>
#include <math.h>
#include <stdint.h>

using namespace nvcuda;

#define BB 4
#define ND 512
#define NT 512
#define DM 256
#define NH 8
#define DK 32

// ---- scratch (static device globals; no runtime allocation) ----
__device__ float g_Q[BB*NH*ND*DK];        // [b,h,n,dk]
__device__ float g_K[BB*NH*NT*DK];        // [b,h,t,dk]
__device__ float g_V[BB*NH*NT*DK];        // [b,h,t,dk]
__device__ float g_ctx[BB*ND*DM];         // [b,n, h*32+dk]
__device__ float g_attout[BB*ND*DM];      // attended (pre-residual)
__device__ float g_xn[BB*ND*DM];          // LayerNorm output
__device__ __half g_trkh[BB*NT*DM];       // tracks in fp16
__device__ __half g_w1h[128*DM];          // w1 in fp16

// ============================================================
// prep: fp32 -> fp16 copies of tracks and w1
// ============================================================
__global__ void prep_half(const float* __restrict__ trk,
                          const float* __restrict__ w1)
{
    int idx = blockIdx.x * 256 + threadIdx.x;   // 0 .. 524287
    g_trkh[idx] = __float2half_rn(trk[idx]);
    if (idx < 128 * DM) g_w1h[idx] = __float2half_rn(w1[idx]);
}

// ============================================================
// QKV GEMM (merged): C[2048,256] = X @ W^T + bias, z selects Q/K/V
// ============================================================
__global__ void qkv_gemm(const float* __restrict__ det,
                         const float* __restrict__ trk,
                         const float* __restrict__ w_q, const float* __restrict__ b_q,
                         const float* __restrict__ w_k, const float* __restrict__ b_k,
                         const float* __restrict__ w_v, const float* __restrict__ b_v)
{
    int z = blockIdx.z;
    const float* X    = (z == 0) ? det : trk;
    const float* W    = (z == 0) ? w_q : (z == 1) ? w_k : w_v;
    const float* bias = (z == 0) ? b_q : (z == 1) ? b_k : b_v;
    float* O          = (z == 0) ? g_Q : (z == 1) ? g_K : g_V;

    __shared__ float Xs[16][65];
    __shared__ float Ws[16][65];
    int tid = threadIdx.x;
    int tx = tid & 15, ty = tid >> 4;
    int m0 = blockIdx.y * 64, n0 = blockIdx.x * 64;

    float acc[4][4] = {};
    for (int k0 = 0; k0 < 256; k0 += 16) {
        #pragma unroll
        for (int r = 0; r < 4; r++) {
            int idx = tid + 256 * r;
            int kk = idx & 15, mm = idx >> 4;
            Xs[kk][mm] = X[(m0 + mm) * 256 + k0 + kk];
            Ws[kk][mm] = W[(n0 + mm) * 256 + k0 + kk];
        }
        __syncthreads();
        #pragma unroll
        for (int kk = 0; kk < 16; kk++) {
            float a[4], b[4];
            #pragma unroll
            for (int i = 0; i < 4; i++) { a[i] = Xs[kk][ty*4+i]; b[i] = Ws[kk][tx*4+i]; }
            #pragma unroll
            for (int i = 0; i < 4; i++)
                #pragma unroll
                for (int j = 0; j < 4; j++)
                    acc[i][j] += a[i] * b[j];
        }
        __syncthreads();
    }
    #pragma unroll
    for (int i = 0; i < 4; i++) {
        int m = m0 + ty*4 + i;
        int b = m >> 9, nn = m & 511;
        #pragma unroll
        for (int j = 0; j < 4; j++) {
            int n = n0 + tx*4 + j;
            int h = n >> 5, dk = n & 31;
            O[((b * NH + h) * 512 + nn) * DK + dk] = acc[i][j] + bias[n];
        }
    }
}

// ============================================================
// output projection GEMM: g_attout = g_ctx @ w_o^T + b_o
// ============================================================
__global__ void gemm_o(const float* __restrict__ W, const float* __restrict__ bias)
{
    const float* X = g_ctx;
    __shared__ float Xs[16][65];
    __shared__ float Ws[16][65];
    int tid = threadIdx.x;
    int tx = tid & 15, ty = tid >> 4;
    int m0 = blockIdx.y * 64, n0 = blockIdx.x * 64;

    float acc[4][4] = {};
    for (int k0 = 0; k0 < 256; k0 += 16) {
        #pragma unroll
        for (int r = 0; r < 4; r++) {
            int idx = tid + 256 * r;
            int kk = idx & 15, mm = idx >> 4;
            Xs[kk][mm] = X[(m0 + mm) * 256 + k0 + kk];
            Ws[kk][mm] = W[(n0 + mm) * 256 + k0 + kk];
        }
        __syncthreads();
        #pragma unroll
        for (int kk = 0; kk < 16; kk++) {
            float a[4], b[4];
            #pragma unroll
            for (int i = 0; i < 4; i++) { a[i] = Xs[kk][ty*4+i]; b[i] = Ws[kk][tx*4+i]; }
            #pragma unroll
            for (int i = 0; i < 4; i++)
                #pragma unroll
                for (int j = 0; j < 4; j++)
                    acc[i][j] += a[i] * b[j];
        }
        __syncthreads();
    }
    #pragma unroll
    for (int i = 0; i < 4; i++) {
        int m = m0 + ty*4 + i;
        #pragma unroll
        for (int j = 0; j < 4; j++) {
            int n = n0 + tx*4 + j;
            g_attout[m * 256 + n] = acc[i][j] + bias[n];
        }
    }
}

// ============================================================
// Fused attention (round-2 version)
// ============================================================
#define ATT_SMEM ((32*512 + 64*33 + 32*33) * 4)

__global__ void fused_attn()
{
    extern __shared__ float sm[];
    float* S  = sm;
    float* KV = sm + 32*512;
    float* Qs = sm + 32*512 + 64*33;

    int b = blockIdx.z, h = blockIdx.y, q0 = blockIdx.x * 32;
    int bh = b * NH + h;
    int tid = threadIdx.x;
    int warp = tid >> 5, lane = tid & 31;

    #pragma unroll
    for (int r = 0; r < 4; r++) {
        int idx = tid + 256 * r;
        int row = idx >> 5, d = idx & 31;
        Qs[row * 33 + d] = g_Q[(bh * ND + q0 + row) * DK + d];
    }

    const float scale = 0.17677669529663689f;

    for (int k0 = 0; k0 < NT; k0 += 64) {
        #pragma unroll
        for (int r = 0; r < 8; r++) {
            int idx = tid + 256 * r;
            int kk = idx >> 5, d = idx & 31;
            KV[kk * 33 + d] = g_K[(bh * NT + k0 + kk) * DK + d];
        }
        __syncthreads();
        float acc[4][2] = {};
        #pragma unroll
        for (int d = 0; d < 32; d++) {
            float kv0 = KV[lane * 33 + d];
            float kv1 = KV[(lane + 32) * 33 + d];
            #pragma unroll
            for (int qi = 0; qi < 4; qi++) {
                float qv = Qs[(warp * 4 + qi) * 33 + d];
                acc[qi][0] += qv * kv0;
                acc[qi][1] += qv * kv1;
            }
        }
        #pragma unroll
        for (int qi = 0; qi < 4; qi++) {
            S[(warp * 4 + qi) * 512 + k0 + lane]      = acc[qi][0] * scale;
            S[(warp * 4 + qi) * 512 + k0 + 32 + lane] = acc[qi][1] * scale;
        }
        __syncthreads();
    }

    #pragma unroll
    for (int qi = 0; qi < 4; qi++) {
        float* row = &S[(warp * 4 + qi) * 512];
        float v[16];
        float m = -1e30f;
        #pragma unroll
        for (int i = 0; i < 16; i++) { v[i] = row[i * 32 + lane]; m = fmaxf(m, v[i]); }
        #pragma unroll
        for (int o = 16; o; o >>= 1) m = fmaxf(m, __shfl_xor_sync(0xffffffffu, m, o));
        float sum = 0.f;
        #pragma unroll
        for (int i = 0; i < 16; i++) { v[i] = __expf(v[i] - m); sum += v[i]; }
        #pragma unroll
        for (int o = 16; o; o >>= 1) sum += __shfl_xor_sync(0xffffffffu, sum, o);
        float inv = 1.f / sum;
        #pragma unroll
        for (int i = 0; i < 16; i++) row[i * 32 + lane] = v[i] * inv;
    }

    float cacc[4] = {};
    for (int k0 = 0; k0 < NT; k0 += 64) {
        __syncthreads();
        #pragma unroll
        for (int r = 0; r < 8; r++) {
            int idx = tid + 256 * r;
            int kk = idx >> 5, d = idx & 31;
            KV[kk * 33 + d] = g_V[(bh * NT + k0 + kk) * DK + d];
        }
        __syncthreads();
        #pragma unroll
        for (int kk = 0; kk < 64; kk++) {
            float vv = KV[kk * 33 + lane];
            #pragma unroll
            for (int qi = 0; qi < 4; qi++)
                cacc[qi] += S[(warp * 4 + qi) * 512 + k0 + kk] * vv;
        }
    }
    #pragma unroll
    for (int qi = 0; qi < 4; qi++) {
        int q = q0 + warp * 4 + qi;
        g_ctx[(b * ND + q) * DM + h * DK + lane] = cacc[qi];
    }
}

// ============================================================
// residual + LayerNorm
// ============================================================
__global__ void ln_kernel(const float* __restrict__ det,
                          const float* __restrict__ ln_g,
                          const float* __restrict__ ln_b)
{
    int row = blockIdx.x, t = threadIdx.x;
    float x = det[row * 256 + t] + g_attout[row * 256 + t];
    float s1 = x, s2 = x * x;
    #pragma unroll
    for (int o = 16; o; o >>= 1) {
        s1 += __shfl_xor_sync(0xffffffffu, s1, o);
        s2 += __shfl_xor_sync(0xffffffffu, s2, o);
    }
    __shared__ float r1[8], r2[8];
    int w = t >> 5, l = t & 31;
    if (!l) { r1[w] = s1; r2[w] = s2; }
    __syncthreads();
    if (w == 0) {
        float a = (l < 8) ? r1[l] : 0.f;
        float c = (l < 8) ? r2[l] : 0.f;
        #pragma unroll
        for (int o = 4; o; o >>= 1) {
            a += __shfl_xor_sync(0xffffffffu, a, o);
            c += __shfl_xor_sync(0xffffffffu, c, o);
        }
        if (!l) { r1[0] = a; r2[0] = c; }
    }
    __syncthreads();
    float mu  = r1[0] * (1.f / 256.f);
    float var = r2[0] * (1.f / 256.f) - mu * mu;
    float xn = (x - mu) * rsqrtf(var + 1e-5f) * ln_g[t] + ln_b[t];
    g_xn[row * 256 + t] = xn;
}

// ============================================================
// Pairwise MLP (fp16 wmma m16n16k16, fp32 accum)
//   block = (t-tile 128, n-chunk of 4, b), 256 thr (8 warps: 4t x 2h)
//   A = tracks fp16 t-tile [128 x 256], resident for all 4 n
//   B = w1h ⊙ xn_h, 4 k-slabs of 64, double-buffered
//   epilogue overlays B buffers
// ============================================================
#define NPER 4
#define ALDH 264                 // A row stride (halves)
#define BLDH 72                  // B slab row stride (halves)
#define ELD  68                  // epilogue row stride (floats)
#define A_BYTES  (128 * ALDH * 2)          // 67584
#define BS_BYTES (128 * BLDH * 2)          // 18432
#define MLP_DYN  (A_BYTES + 2 * BS_BYTES)  // 104448

__global__ void __launch_bounds__(256, 2)
mlp_fp16(const float* __restrict__ b1,
         const float* __restrict__ w2,
         const float* __restrict__ b2,
         float* __restrict__ out)
{
    extern __shared__ __align__(16) char dyn[];
    __half* As  = (__half*)dyn;
    __half* Bs0 = (__half*)(dyn + A_BYTES);
    __half* Bs1 = (__half*)(dyn + A_BYTES + BS_BYTES);
    float*  E   = (float*)(dyn + A_BYTES);          // overlay

    __shared__ __half2 xnh2[128];
    __shared__ float b1s[128], w2s[128];

    int b  = blockIdx.z;
    int t0 = blockIdx.x * 128;
    int n0 = blockIdx.y * NPER;
    int tid = threadIdx.x;
    int warp = tid >> 5, lane = tid & 31;
    int wt = (warp & 3) * 32;    // t offset
    int wh = (warp >> 2) * 64;   // h offset (0 or 64)

    if (tid < 128) { b1s[tid] = b1[tid]; w2s[tid] = w2[tid]; }
    float bias2 = b2[0];

    // ---- stage A (tracks fp16 tile) once ----
    const __half* trkh = g_trkh + ((size_t)(b * NT + t0)) * 256;
    #pragma unroll
    for (int i = 0; i < 16; i++) {
        int idx = tid + i * 256;         // 4096 uint4 groups (8 halves)
        int row = idx >> 5;
        int kg  = idx & 31;
        uint4 v = *reinterpret_cast<const uint4*>(trkh + row * 256 + kg * 8);
        *reinterpret_cast<uint4*>(As + row * ALDH + kg * 8) = v;
    }

    for (int ni = 0; ni < NPER; ni++) {
        int n = n0 + ni;
        if (tid < 128) {
            float2 x2 = *reinterpret_cast<const float2*>(
                g_xn + ((size_t)(b * ND + n)) * 256 + tid * 2);
            xnh2[tid] = __floats2half2_rn(x2.x, x2.y);
        }

        wmma::fragment<wmma::accumulator, 16, 16, 16, float> cf[2][4];
        #pragma unroll
        for (int i = 0; i < 2; i++)
            #pragma unroll
            for (int j = 0; j < 4; j++) wmma::fill_fragment(cf[i][j], 0.f);

        __syncthreads();   // xnh2 visible; E region free; A visible (first n)

        // stage slab 0
        #pragma unroll
        for (int i = 0; i < 16; i++) {
            int idx = tid + i * 256;     // 4096 half2
            int h  = idx >> 5;
            int kp = idx & 31;
            __half2 wv = *reinterpret_cast<const __half2*>(g_w1h + h * 256 + kp * 2);
            Bs0[h * BLDH + kp * 2] = __low2half(__hmul2(wv, xnh2[kp]));
            *reinterpret_cast<__half2*>(Bs0 + h * BLDH + kp * 2) =
                __hmul2(wv, xnh2[kp]);
        }
        __syncthreads();

        #pragma unroll
        for (int s = 0; s < 4; s++) {
            __half* cur = (s & 1) ? Bs1 : Bs0;
            if (s < 3) {
                __half* nxt = (s & 1) ? Bs0 : Bs1;
                int k0n = (s + 1) * 64;
                #pragma unroll
                for (int i = 0; i < 16; i++) {
                    int idx = tid + i * 256;
                    int h  = idx >> 5;
                    int kp = idx & 31;
                    __half2 wv = *reinterpret_cast<const __half2*>(
                        g_w1h + h * 256 + k0n + kp * 2);
                    *reinterpret_cast<__half2*>(nxt + h * BLDH + kp * 2) =
                        __hmul2(wv, xnh2[(k0n >> 1) + kp]);
                }
            }
            int kbase = s * 64;
            #pragma unroll
            for (int ks = 0; ks < 4; ks++) {
                wmma::fragment<wmma::matrix_a, 16, 16, 16, __half, wmma::row_major> af[2];
                #pragma unroll
                for (int i = 0; i < 2; i++)
                    wmma::load_matrix_sync(af[i],
                        As + (wt + 16*i) * ALDH + kbase + ks * 16, ALDH);
                #pragma unroll
                for (int j = 0; j < 4; j++) {
                    wmma::fragment<wmma::matrix_b, 16, 16, 16, __half, wmma::col_major> bf;
                    wmma::load_matrix_sync(bf,
                        cur + (wh + 16*j) * BLDH + ks * 16, BLDH);
                    wmma::mma_sync(cf[0][j], af[0], bf, cf[0][j]);
                    wmma::mma_sync(cf[1][j], af[1], bf, cf[1][j]);
                }
            }
            __syncthreads();
        }

        // ---- epilogue: two h-half passes through E (overlaid on Bs) ----
        float part[16];

        if (warp < 4) {
            #pragma unroll
            for (int i = 0; i < 2; i++)
                #pragma unroll
                for (int j = 0; j < 4; j++)
                    wmma::store_matrix_sync(&E[(wt + 16*i) * ELD + 16*j], cf[i][j],
                                            ELD, wmma::mem_row_major);
        }
        __syncthreads();
        #pragma unroll
        for (int r = 0; r < 16; r++) {
            int t = warp * 16 + r;
            float v0 = E[t * ELD + lane]      + b1s[lane];
            float v1 = E[t * ELD + 32 + lane] + b1s[32 + lane];
            part[r] = fmaxf(v0, 0.f) * w2s[lane] + fmaxf(v1, 0.f) * w2s[32 + lane];
        }
        __syncthreads();

        if (warp >= 4) {
            #pragma unroll
            for (int i = 0; i < 2; i++)
                #pragma unroll
                for (int j = 0; j < 4; j++)
                    wmma::store_matrix_sync(&E[(wt + 16*i) * ELD + 16*j], cf[i][j],
                                            ELD, wmma::mem_row_major);
        }
        __syncthreads();
        #pragma unroll
        for (int r = 0; r < 16; r++) {
            int t = warp * 16 + r;
            float v0 = E[t * ELD + lane]      + b1s[64 + lane];
            float v1 = E[t * ELD + 32 + lane] + b1s[96 + lane];
            part[r] += fmaxf(v0, 0.f) * w2s[64 + lane] + fmaxf(v1, 0.f) * w2s[96 + lane];
            #pragma unroll
            for (int o = 16; o; o >>= 1)
                part[r] += __shfl_xor_sync(0xffffffffu, part[r], o);
            if (lane == 0) {
                float logit = part[r] + bias2;
                out[((size_t)(b * ND + n)) * NT + t0 + warp * 16 + r] =
                    1.f / (1.f + __expf(-logit));
            }
        }
    }
}

// ============================================================
extern "C" void kernel_launch(void* const* d_in, const int* in_sizes, int n_in,
                              void* d_out, int out_size)
{
    const float* det  = (const float*)d_in[0];
    const float* trk  = (const float*)d_in[1];
    const float* w_q  = (const float*)d_in[2];
    const float* b_q  = (const float*)d_in[3];
    const float* w_k  = (const float*)d_in[4];
    const float* b_k  = (const float*)d_in[5];
    const float* w_v  = (const float*)d_in[6];
    const float* b_v  = (const float*)d_in[7];
    const float* w_o  = (const float*)d_in[8];
    const float* b_o  = (const float*)d_in[9];
    const float* ln_g = (const float*)d_in[10];
    const float* ln_b = (const float*)d_in[11];
    const float* w1   = (const float*)d_in[12];
    const float* b1   = (const float*)d_in[13];
    const float* w2   = (const float*)d_in[14];
    const float* b2   = (const float*)d_in[15];
    float* out = (float*)d_out;

    cudaFuncSetAttribute(mlp_fp16,
                         cudaFuncAttributeMaxDynamicSharedMemorySize, MLP_DYN);
    cudaFuncSetAttribute(fused_attn,
                         cudaFuncAttributeMaxDynamicSharedMemorySize, ATT_SMEM);

    prep_half<<<2048, 256>>>(trk, w1);
    qkv_gemm<<<dim3(4, 32, 3), 256>>>(det, trk, w_q, b_q, w_k, b_k, w_v, b_v);
    fused_attn<<<dim3(16, NH, BB), 256, ATT_SMEM>>>();
    gemm_o<<<dim3(4, 32), 256>>>(w_o, b_o);
    ln_kernel<<<BB * ND, 256>>>(det, ln_g, ln_b);
    mlp_fp16<<<dim3(4, ND / NPER, BB), 256, MLP_DYN>>>(b1, w2, b2, out);
}

// round 7
// speedup vs baseline: 4.6123x; 1.5757x over previous
#include <cuda_runtime.h>
#include <cuda_fp16.h>
#include <math.h>
#include <stdint.h>

#define BB 4
#define ND 512
#define NT 512
#define DM 256
#define NH 8
#define DK 32

// ---- scratch (static device globals; no runtime allocation) ----
__device__ float g_Q[BB*NH*ND*DK];        // [b,h,n,dk]
__device__ float g_K[BB*NH*NT*DK];        // [b,h,t,dk]
__device__ float g_V[BB*NH*NT*DK];        // [b,h,t,dk]
__device__ float g_ctx[BB*ND*DM];         // [b,n, h*32+dk]
__device__ float g_attout[BB*ND*DM];      // attended (pre-residual)
__device__ float g_xn[BB*ND*DM];          // LayerNorm output (fp32)
__device__ __half g_xnh[BB*ND*DM];        // LayerNorm output (fp16)
__device__ __half g_trkh[BB*NT*DM];       // tracks in fp16
__device__ __half g_w1h[128*DM];          // w1 in fp16

static __device__ __forceinline__ uint32_t sm_u32(const void* p) {
    uint32_t a;
    asm("{ .reg .u64 t; cvta.to.shared.u64 t, %1; cvt.u32.u64 %0, t; }"
        : "=r"(a) : "l"(p));
    return a;
}

#define LDSM_X4(r, addr) \
    asm volatile("ldmatrix.sync.aligned.m8n8.x4.shared.b16 {%0,%1,%2,%3}, [%4];" \
        : "=r"((r)[0]), "=r"((r)[1]), "=r"((r)[2]), "=r"((r)[3]) : "r"(addr))
#define MMA16816(c, a, b0, b1) \
    asm volatile("mma.sync.aligned.m16n8k16.row.col.f32.f16.f16.f32 " \
        "{%0,%1,%2,%3}, {%4,%5,%6,%7}, {%8,%9}, {%0,%1,%2,%3};" \
        : "+f"((c)[0]), "+f"((c)[1]), "+f"((c)[2]), "+f"((c)[3]) \
        : "r"((a)[0]), "r"((a)[1]), "r"((a)[2]), "r"((a)[3]), "r"(b0), "r"(b1))

// ============================================================
// prep: fp32 -> fp16 copies of tracks and w1
// ============================================================
__global__ void prep_half(const float* __restrict__ trk,
                          const float* __restrict__ w1)
{
    int idx = blockIdx.x * 256 + threadIdx.x;   // 0 .. 524287
    g_trkh[idx] = __float2half_rn(trk[idx]);
    if (idx < 128 * DM) g_w1h[idx] = __float2half_rn(w1[idx]);
}

// ============================================================
// QKV GEMM (merged): C[2048,256] = X @ W^T + bias, z selects Q/K/V
// ============================================================
__global__ void qkv_gemm(const float* __restrict__ det,
                         const float* __restrict__ trk,
                         const float* __restrict__ w_q, const float* __restrict__ b_q,
                         const float* __restrict__ w_k, const float* __restrict__ b_k,
                         const float* __restrict__ w_v, const float* __restrict__ b_v)
{
    int z = blockIdx.z;
    const float* X    = (z == 0) ? det : trk;
    const float* W    = (z == 0) ? w_q : (z == 1) ? w_k : w_v;
    const float* bias = (z == 0) ? b_q : (z == 1) ? b_k : b_v;
    float* O          = (z == 0) ? g_Q : (z == 1) ? g_K : g_V;

    __shared__ float Xs[16][65];
    __shared__ float Ws[16][65];
    int tid = threadIdx.x;
    int tx = tid & 15, ty = tid >> 4;
    int m0 = blockIdx.y * 64, n0 = blockIdx.x * 64;

    float acc[4][4] = {};
    for (int k0 = 0; k0 < 256; k0 += 16) {
        #pragma unroll
        for (int r = 0; r < 4; r++) {
            int idx = tid + 256 * r;
            int kk = idx & 15, mm = idx >> 4;
            Xs[kk][mm] = X[(m0 + mm) * 256 + k0 + kk];
            Ws[kk][mm] = W[(n0 + mm) * 256 + k0 + kk];
        }
        __syncthreads();
        #pragma unroll
        for (int kk = 0; kk < 16; kk++) {
            float a[4], b[4];
            #pragma unroll
            for (int i = 0; i < 4; i++) { a[i] = Xs[kk][ty*4+i]; b[i] = Ws[kk][tx*4+i]; }
            #pragma unroll
            for (int i = 0; i < 4; i++)
                #pragma unroll
                for (int j = 0; j < 4; j++)
                    acc[i][j] += a[i] * b[j];
        }
        __syncthreads();
    }
    #pragma unroll
    for (int i = 0; i < 4; i++) {
        int m = m0 + ty*4 + i;
        int b = m >> 9, nn = m & 511;
        #pragma unroll
        for (int j = 0; j < 4; j++) {
            int n = n0 + tx*4 + j;
            int h = n >> 5, dk = n & 31;
            O[((b * NH + h) * 512 + nn) * DK + dk] = acc[i][j] + bias[n];
        }
    }
}

// ============================================================
// output projection GEMM: g_attout = g_ctx @ w_o^T + b_o
// ============================================================
__global__ void gemm_o(const float* __restrict__ W, const float* __restrict__ bias)
{
    const float* X = g_ctx;
    __shared__ float Xs[16][65];
    __shared__ float Ws[16][65];
    int tid = threadIdx.x;
    int tx = tid & 15, ty = tid >> 4;
    int m0 = blockIdx.y * 64, n0 = blockIdx.x * 64;

    float acc[4][4] = {};
    for (int k0 = 0; k0 < 256; k0 += 16) {
        #pragma unroll
        for (int r = 0; r < 4; r++) {
            int idx = tid + 256 * r;
            int kk = idx & 15, mm = idx >> 4;
            Xs[kk][mm] = X[(m0 + mm) * 256 + k0 + kk];
            Ws[kk][mm] = W[(n0 + mm) * 256 + k0 + kk];
        }
        __syncthreads();
        #pragma unroll
        for (int kk = 0; kk < 16; kk++) {
            float a[4], b[4];
            #pragma unroll
            for (int i = 0; i < 4; i++) { a[i] = Xs[kk][ty*4+i]; b[i] = Ws[kk][tx*4+i]; }
            #pragma unroll
            for (int i = 0; i < 4; i++)
                #pragma unroll
                for (int j = 0; j < 4; j++)
                    acc[i][j] += a[i] * b[j];
        }
        __syncthreads();
    }
    #pragma unroll
    for (int i = 0; i < 4; i++) {
        int m = m0 + ty*4 + i;
        #pragma unroll
        for (int j = 0; j < 4; j++) {
            int n = n0 + tx*4 + j;
            g_attout[m * 256 + n] = acc[i][j] + bias[n];
        }
    }
}

// ============================================================
// Fused attention v2: float4 smem, 3-buffer K/V staging, 2 CTA/SM
//   block = (qtile 32, h, b), 256 threads
// ============================================================
#define KVS (64 * 36)
#define ATT_SMEM ((32*512 + 3*KVS + 32*36) * 4)

__global__ void __launch_bounds__(256, 2) fused_attn()
{
    extern __shared__ float sm[];
    float* S  = sm;                       // [32][512]
    float* KV = sm + 32*512;              // [3][64][36]
    float* Qs = sm + 32*512 + 3*KVS;      // [32][36]

    int b = blockIdx.z, h = blockIdx.y, q0 = blockIdx.x * 32;
    int bh = b * NH + h;
    int tid = threadIdx.x;
    int warp = tid >> 5, lane = tid & 31;

    // stage Q tile [32][32] as float4
    {
        int row = tid >> 3, f4 = tid & 7;
        *(float4*)&Qs[row * 36 + f4 * 4] =
            *(const float4*)&g_Q[((size_t)(bh * ND + q0 + row)) * DK + f4 * 4];
    }
    // stage K chunk 0
    #pragma unroll
    for (int i = 0; i < 2; i++) {
        int idx = tid + i * 256;
        int row = idx >> 3, f4 = idx & 7;
        *(float4*)&KV[row * 36 + f4 * 4] =
            *(const float4*)&g_K[((size_t)(bh * NT + row)) * DK + f4 * 4];
    }

    const float scale = 0.17677669529663689f;  // 1/sqrt(32)

    // ---- scores ----
    for (int c = 0; c < 8; c++) {
        if (c < 7) {
            float* dst = KV + ((c + 1) % 3) * KVS;
            #pragma unroll
            for (int i = 0; i < 2; i++) {
                int idx = tid + i * 256;
                int row = idx >> 3, f4 = idx & 7;
                *(float4*)&dst[row * 36 + f4 * 4] =
                    *(const float4*)&g_K[((size_t)(bh * NT + (c + 1) * 64 + row)) * DK + f4 * 4];
            }
        }
        __syncthreads();
        const float* Kb = KV + (c % 3) * KVS;
        float acc[4][2] = {};
        #pragma unroll
        for (int d4 = 0; d4 < 8; d4++) {
            float4 k0v = *(const float4*)&Kb[lane * 36 + d4 * 4];
            float4 k1v = *(const float4*)&Kb[(lane + 32) * 36 + d4 * 4];
            #pragma unroll
            for (int qi = 0; qi < 4; qi++) {
                float4 qv = *(const float4*)&Qs[(warp * 4 + qi) * 36 + d4 * 4];
                acc[qi][0] += qv.x*k0v.x + qv.y*k0v.y + qv.z*k0v.z + qv.w*k0v.w;
                acc[qi][1] += qv.x*k1v.x + qv.y*k1v.y + qv.z*k1v.z + qv.w*k1v.w;
            }
        }
        #pragma unroll
        for (int qi = 0; qi < 4; qi++) {
            S[(warp * 4 + qi) * 512 + c * 64 + lane]      = acc[qi][0] * scale;
            S[(warp * 4 + qi) * 512 + c * 64 + 32 + lane] = acc[qi][1] * scale;
        }
    }
    __syncthreads();   // all scores done before V staging reuses KV

    // ---- softmax (warp-local rows) ----
    #pragma unroll
    for (int qi = 0; qi < 4; qi++) {
        float* row = &S[(warp * 4 + qi) * 512];
        float v[16];
        float m = -1e30f;
        #pragma unroll
        for (int i = 0; i < 16; i++) { v[i] = row[i * 32 + lane]; m = fmaxf(m, v[i]); }
        #pragma unroll
        for (int o = 16; o; o >>= 1) m = fmaxf(m, __shfl_xor_sync(0xffffffffu, m, o));
        float sum = 0.f;
        #pragma unroll
        for (int i = 0; i < 16; i++) { v[i] = __expf(v[i] - m); sum += v[i]; }
        #pragma unroll
        for (int o = 16; o; o >>= 1) sum += __shfl_xor_sync(0xffffffffu, sum, o);
        float inv = 1.f / sum;
        #pragma unroll
        for (int i = 0; i < 16; i++) row[i * 32 + lane] = v[i] * inv;
    }

    // ---- ctx = S @ V ----
    // stage V chunk 0
    #pragma unroll
    for (int i = 0; i < 2; i++) {
        int idx = tid + i * 256;
        int row = idx >> 3, f4 = idx & 7;
        *(float4*)&KV[row * 36 + f4 * 4] =
            *(const float4*)&g_V[((size_t)(bh * NT + row)) * DK + f4 * 4];
    }
    float cacc[4] = {};
    for (int c = 0; c < 8; c++) {
        if (c < 7) {
            float* dst = KV + ((c + 1) % 3) * KVS;
            #pragma unroll
            for (int i = 0; i < 2; i++) {
                int idx = tid + i * 256;
                int row = idx >> 3, f4 = idx & 7;
                *(float4*)&dst[row * 36 + f4 * 4] =
                    *(const float4*)&g_V[((size_t)(bh * NT + (c + 1) * 64 + row)) * DK + f4 * 4];
            }
        }
        __syncthreads();
        const float* Vb = KV + (c % 3) * KVS;
        #pragma unroll
        for (int k4 = 0; k4 < 16; k4++) {
            float v0 = Vb[(k4 * 4 + 0) * 36 + lane];
            float v1 = Vb[(k4 * 4 + 1) * 36 + lane];
            float v2 = Vb[(k4 * 4 + 2) * 36 + lane];
            float v3 = Vb[(k4 * 4 + 3) * 36 + lane];
            #pragma unroll
            for (int qi = 0; qi < 4; qi++) {
                float4 sv = *(const float4*)&S[(warp * 4 + qi) * 512 + c * 64 + k4 * 4];
                cacc[qi] += sv.x*v0 + sv.y*v1 + sv.z*v2 + sv.w*v3;
            }
        }
    }
    #pragma unroll
    for (int qi = 0; qi < 4; qi++) {
        int q = q0 + warp * 4 + qi;
        g_ctx[(b * ND + q) * DM + h * DK + lane] = cacc[qi];
    }
}

// ============================================================
// residual + LayerNorm (also emits fp16 xn)
// ============================================================
__global__ void ln_kernel(const float* __restrict__ det,
                          const float* __restrict__ ln_g,
                          const float* __restrict__ ln_b)
{
    int row = blockIdx.x, t = threadIdx.x;
    float x = det[row * 256 + t] + g_attout[row * 256 + t];
    float s1 = x, s2 = x * x;
    #pragma unroll
    for (int o = 16; o; o >>= 1) {
        s1 += __shfl_xor_sync(0xffffffffu, s1, o);
        s2 += __shfl_xor_sync(0xffffffffu, s2, o);
    }
    __shared__ float r1[8], r2[8];
    int w = t >> 5, l = t & 31;
    if (!l) { r1[w] = s1; r2[w] = s2; }
    __syncthreads();
    if (w == 0) {
        float a = (l < 8) ? r1[l] : 0.f;
        float c = (l < 8) ? r2[l] : 0.f;
        #pragma unroll
        for (int o = 4; o; o >>= 1) {
            a += __shfl_xor_sync(0xffffffffu, a, o);
            c += __shfl_xor_sync(0xffffffffu, c, o);
        }
        if (!l) { r1[0] = a; r2[0] = c; }
    }
    __syncthreads();
    float mu  = r1[0] * (1.f / 256.f);
    float var = r2[0] * (1.f / 256.f) - mu * mu;
    float xn = (x - mu) * rsqrtf(var + 1e-5f) * ln_g[t] + ln_b[t];
    g_xn[row * 256 + t] = xn;
    g_xnh[row * 256 + t] = __float2half_rn(xn);
}

// ============================================================
// Pairwise MLP v3b: raw mma.sync m16n8k16, register epilogue
//   B stored [h][k] row-major == col-major k x n  -> NON-trans ldmatrix
// ============================================================
#define NPER 8
#define ALDH 264
#define BLDH 264
#define MLP_DYN (128 * ALDH * 2 + 128 * BLDH * 2)   // 135168

__global__ void __launch_bounds__(256, 1)
mlp_mma(const float* __restrict__ b1,
        const float* __restrict__ w2,
        const float* __restrict__ b2,
        float* __restrict__ out)
{
    extern __shared__ __align__(16) char dyn[];
    __half* As = (__half*)dyn;                     // [128][ALDH]
    __half* Bs = (__half*)(dyn + 128 * ALDH * 2);  // [128][BLDH]
    __shared__ float b1s[128], w2s[128], psum[128];

    int b  = blockIdx.z;
    int t0 = blockIdx.x * 128;
    int n0 = blockIdx.y * NPER;
    int tid = threadIdx.x;
    int warp = tid >> 5, lane = tid & 31;
    int wt = (warp & 3) * 32;    // t offset
    int wh = (warp >> 2) * 64;   // h offset (0 or 64)
    int tg = lane & 3, g = lane >> 2;

    if (tid < 128) { b1s[tid] = b1[tid]; w2s[tid] = w2[tid]; }
    float bias2 = b2[0];

    // ---- stage A (tracks fp16 tile) once ----
    const __half* trkh = g_trkh + ((size_t)(b * NT + t0)) * 256;
    #pragma unroll
    for (int i = 0; i < 16; i++) {
        int idx = tid + i * 256;
        int row = idx >> 5, kg = idx & 31;
        *(uint4*)(As + row * ALDH + kg * 8) =
            *(const uint4*)(trkh + row * 256 + kg * 8);
    }

    // ldmatrix lane base addresses
    // A: m0=rows0-7/k0-7, m1=rows8-15/k0-7, m2=rows0-7/k8-15, m3=rows8-15/k8-15
    uint32_t a_base = sm_u32(As) +
        (((wt + (lane & 15)) * ALDH + (lane >> 4) * 8) << 1);
    // B: m0=n0-7/k0-7, m1=n0-7/k8-15, m2=n8-15/k0-7, m3=n8-15/k8-15
    uint32_t b_base = sm_u32(Bs) +
        (((wh + ((lane >> 4) << 3) + (lane & 7)) * BLDH + ((lane >> 3) & 1) * 8) << 1);

    for (int ni = 0; ni < NPER; ni++) {
        int n = n0 + ni;

        // ---- stage B = w1h ⊙ xnh(n) ----
        const __half* xh = g_xnh + ((size_t)(b * ND + n)) * 256;
        #pragma unroll
        for (int i = 0; i < 16; i++) {
            int idx = tid + i * 256;
            int hrow = idx >> 5, kg = idx & 31;
            uint4 wv = *(const uint4*)(g_w1h + hrow * 256 + kg * 8);
            uint4 xv = *(const uint4*)(xh + kg * 8);
            __half2* wp = (__half2*)&wv;
            const __half2* xp = (const __half2*)&xv;
            wp[0] = __hmul2(wp[0], xp[0]); wp[1] = __hmul2(wp[1], xp[1]);
            wp[2] = __hmul2(wp[2], xp[2]); wp[3] = __hmul2(wp[3], xp[3]);
            *(uint4*)(Bs + hrow * BLDH + kg * 8) = wv;
        }
        __syncthreads();   // B (and A, psum-reuse) ready

        float c[2][8][4];
        #pragma unroll
        for (int mi = 0; mi < 2; mi++)
            #pragma unroll
            for (int nj = 0; nj < 8; nj++)
                #pragma unroll
                for (int k = 0; k < 4; k++) c[mi][nj][k] = 0.f;

        #pragma unroll
        for (int kk = 0; kk < 16; kk++) {
            uint32_t a[2][4];
            LDSM_X4(a[0], a_base + kk * 32);
            LDSM_X4(a[1], a_base + 16 * ALDH * 2 + kk * 32);
            uint32_t bb[4][4];
            #pragma unroll
            for (int p = 0; p < 4; p++)
                LDSM_X4(bb[p], b_base + p * 16 * BLDH * 2 + kk * 32);
            #pragma unroll
            for (int mi = 0; mi < 2; mi++)
                #pragma unroll
                for (int nj = 0; nj < 8; nj++)
                    MMA16816(c[mi][nj], a[mi],
                             bb[nj >> 1][(nj & 1) * 2], bb[nj >> 1][(nj & 1) * 2 + 1]);
        }

        // ---- register epilogue ----
        float sreg[2][2];
        #pragma unroll
        for (int mi = 0; mi < 2; mi++) {
            float s0 = 0.f, s1 = 0.f;
            #pragma unroll
            for (int nj = 0; nj < 8; nj++) {
                int col0 = wh + nj * 8 + tg * 2;
                float bb0 = b1s[col0], ww0 = w2s[col0];
                float bb1 = b1s[col0 + 1], ww1 = w2s[col0 + 1];
                s0 += fmaxf(c[mi][nj][0] + bb0, 0.f) * ww0
                    + fmaxf(c[mi][nj][1] + bb1, 0.f) * ww1;
                s1 += fmaxf(c[mi][nj][2] + bb0, 0.f) * ww0
                    + fmaxf(c[mi][nj][3] + bb1, 0.f) * ww1;
            }
            s0 += __shfl_xor_sync(0xffffffffu, s0, 1);
            s0 += __shfl_xor_sync(0xffffffffu, s0, 2);
            s1 += __shfl_xor_sync(0xffffffffu, s1, 1);
            s1 += __shfl_xor_sync(0xffffffffu, s1, 2);
            sreg[mi][0] = s0; sreg[mi][1] = s1;
            if (warp >= 4 && tg == 0) {
                psum[wt + mi * 16 + g]     = s0;
                psum[wt + mi * 16 + g + 8] = s1;
            }
        }
        __syncthreads();   // psum ready
        if (warp < 4 && tg == 0) {
            #pragma unroll
            for (int mi = 0; mi < 2; mi++) {
                int t = wt + mi * 16 + g;
                float l0 = sreg[mi][0] + psum[t]     + bias2;
                float l1 = sreg[mi][1] + psum[t + 8] + bias2;
                size_t base = ((size_t)(b * ND + n)) * NT + t0;
                out[base + t]     = 1.f / (1.f + __expf(-l0));
                out[base + t + 8] = 1.f / (1.f + __expf(-l1));
            }
        }
    }
}

// ============================================================
extern "C" void kernel_launch(void* const* d_in, const int* in_sizes, int n_in,
                              void* d_out, int out_size)
{
    const float* det  = (const float*)d_in[0];
    const float* trk  = (const float*)d_in[1];
    const float* w_q  = (const float*)d_in[2];
    const float* b_q  = (const float*)d_in[3];
    const float* w_k  = (const float*)d_in[4];
    const float* b_k  = (const float*)d_in[5];
    const float* w_v  = (const float*)d_in[6];
    const float* b_v  = (const float*)d_in[7];
    const float* w_o  = (const float*)d_in[8];
    const float* b_o  = (const float*)d_in[9];
    const float* ln_g = (const float*)d_in[10];
    const float* ln_b = (const float*)d_in[11];
    const float* w1   = (const float*)d_in[12];
    const float* b1   = (const float*)d_in[13];
    const float* w2   = (const float*)d_in[14];
    const float* b2   = (const float*)d_in[15];
    float* out = (float*)d_out;

    cudaFuncSetAttribute(mlp_mma,
                         cudaFuncAttributeMaxDynamicSharedMemorySize, MLP_DYN);
    cudaFuncSetAttribute(fused_attn,
                         cudaFuncAttributeMaxDynamicSharedMemorySize, ATT_SMEM);

    prep_half<<<2048, 256>>>(trk, w1);
    qkv_gemm<<<dim3(4, 32, 3), 256>>>(det, trk, w_q, b_q, w_k, b_k, w_v, b_v);
    fused_attn<<<dim3(16, NH, BB), 256, ATT_SMEM>>>();
    gemm_o<<<dim3(4, 32), 256>>>(w_o, b_o);
    ln_kernel<<<BB * ND, 256>>>(det, ln_g, ln_b);
    mlp_mma<<<dim3(4, ND / NPER, BB), 256, MLP_DYN>>>(b1, w2, b2, out);
}

// round 8
// speedup vs baseline: 6.6094x; 1.4330x over previous
#include <cuda_runtime.h>
#include <cuda_fp16.h>
#include <math.h>
#include <stdint.h>

#define BB 4
#define ND 512
#define NT 512
#define DM 256
#define NH 8
#define DK 32

// ---- scratch (static device globals; no runtime allocation) ----
__device__ __half g_deth[BB*ND*DM];       // detections fp16
__device__ __half g_trkh[BB*NT*DM];       // tracks fp16
__device__ __half g_wqh[DM*DM], g_wkh[DM*DM], g_wvh[DM*DM], g_woh[DM*DM];
__device__ __half g_w1h[128*DM];
__device__ __half g_Qh[BB*NH*ND*DK];      // [bh][q][dk]
__device__ __half g_Kh[BB*NH*NT*DK];      // [bh][t][dk]
__device__ __half g_Vht[BB*NH*DK*NT];     // [bh][dk][t]  (transposed)
__device__ __half g_ctxh[BB*ND*DM];       // attention output fp16 [token][256]
__device__ float g_attout[BB*ND*DM];      // attended (pre-residual)
__device__ float g_xn[BB*ND*DM];          // LayerNorm output (fp32)
__device__ __half g_xnh[BB*ND*DM];        // LayerNorm output (fp16)

static __device__ __forceinline__ uint32_t sm_u32(const void* p) {
    uint32_t a;
    asm("{ .reg .u64 t; cvta.to.shared.u64 t, %1; cvt.u32.u64 %0, t; }"
        : "=r"(a) : "l"(p));
    return a;
}
static __device__ __forceinline__ uint32_t f2h2(float a, float b) {
    __half2 h = __floats2half2_rn(a, b);
    return *reinterpret_cast<uint32_t*>(&h);
}

#define LDSM_X4(r, addr) \
    asm volatile("ldmatrix.sync.aligned.m8n8.x4.shared.b16 {%0,%1,%2,%3}, [%4];" \
        : "=r"((r)[0]), "=r"((r)[1]), "=r"((r)[2]), "=r"((r)[3]) : "r"(addr))
#define MMA16816(c, a, b0, b1) \
    asm volatile("mma.sync.aligned.m16n8k16.row.col.f32.f16.f16.f32 " \
        "{%0,%1,%2,%3}, {%4,%5,%6,%7}, {%8,%9}, {%0,%1,%2,%3};" \
        : "+f"((c)[0]), "+f"((c)[1]), "+f"((c)[2]), "+f"((c)[3]) \
        : "r"((a)[0]), "r"((a)[1]), "r"((a)[2]), "r"((a)[3]), "r"(b0), "r"(b1))

// ============================================================
// prep: fp32 -> fp16 copies
// ============================================================
__global__ void prep_half(const float* __restrict__ det,
                          const float* __restrict__ trk,
                          const float* __restrict__ w_q, const float* __restrict__ w_k,
                          const float* __restrict__ w_v, const float* __restrict__ w_o,
                          const float* __restrict__ w1)
{
    int idx = blockIdx.x * 256 + threadIdx.x;   // 0 .. 524287
    g_deth[idx] = __float2half_rn(det[idx]);
    g_trkh[idx] = __float2half_rn(trk[idx]);
    if (idx < DM * DM) {
        g_wqh[idx] = __float2half_rn(w_q[idx]);
        g_wkh[idx] = __float2half_rn(w_k[idx]);
        g_wvh[idx] = __float2half_rn(w_v[idx]);
        g_woh[idx] = __float2half_rn(w_o[idx]);
    }
    if (idx < 128 * DM) g_w1h[idx] = __float2half_rn(w1[idx]);
}

// ============================================================
// Projection GEMM (fp16 mma): C[2048,256] = X @ W^T + bias
//   z = 0: Q (det,w_q) -> g_Qh [bh][q][dk]
//   z = 1: K (trk,w_k) -> g_Kh [bh][t][dk]
//   z = 2: V (trk,w_v) -> g_Vht [bh][dk][t] (transposed)
// block: m-tile 64, n-tile 128; 256 thr = 8 warps (4m x 2n)
// ============================================================
#define PALD 264
#define PROJ_SMEM ((64 * PALD + 128 * PALD) * 2)   // 101376

__global__ void __launch_bounds__(256)
proj_gemm(const float* __restrict__ b_q, const float* __restrict__ b_k,
          const float* __restrict__ b_v)
{
    int z = blockIdx.z;
    const __half* X = (z == 0) ? g_deth : g_trkh;
    const __half* W = (z == 0) ? g_wqh : (z == 1) ? g_wkh : g_wvh;
    const float* bias = (z == 0) ? b_q : (z == 1) ? b_k : b_v;

    extern __shared__ __align__(16) char dyn[];
    __half* As = (__half*)dyn;                      // [64][PALD]
    __half* Bs = (__half*)(dyn + 64 * PALD * 2);    // [128][PALD]

    int tid = threadIdx.x;
    int warp = tid >> 5, lane = tid & 31;
    int m0 = blockIdx.x * 64, n0blk = blockIdx.y * 128;
    int wm = (warp & 3) * 16, wn = (warp >> 2) * 64;
    int tg = lane & 3, g = lane >> 2;

    #pragma unroll
    for (int i = 0; i < 8; i++) {
        int idx = tid + i * 256;          // 2048 uint4
        int row = idx >> 5, kg = idx & 31;
        *(uint4*)(As + row * PALD + kg * 8) =
            *(const uint4*)(X + (size_t)(m0 + row) * 256 + kg * 8);
    }
    #pragma unroll
    for (int i = 0; i < 16; i++) {
        int idx = tid + i * 256;          // 4096 uint4
        int row = idx >> 5, kg = idx & 31;
        *(uint4*)(Bs + row * PALD + kg * 8) =
            *(const uint4*)(W + (size_t)(n0blk + row) * 256 + kg * 8);
    }
    __syncthreads();

    uint32_t a_base = sm_u32(As) + (((wm + (lane & 15)) * PALD + (lane >> 4) * 8) << 1);
    uint32_t b_base = sm_u32(Bs) +
        (((wn + ((lane >> 4) << 3) + (lane & 7)) * PALD + ((lane >> 3) & 1) * 8) << 1);

    float c[8][4];
    #pragma unroll
    for (int nj = 0; nj < 8; nj++)
        #pragma unroll
        for (int k = 0; k < 4; k++) c[nj][k] = 0.f;

    #pragma unroll
    for (int kt = 0; kt < 16; kt++) {
        uint32_t a[4];
        LDSM_X4(a, a_base + kt * 32);
        uint32_t bb[4][4];
        #pragma unroll
        for (int p = 0; p < 4; p++)
            LDSM_X4(bb[p], b_base + p * 16 * PALD * 2 + kt * 32);
        #pragma unroll
        for (int nj = 0; nj < 8; nj++)
            MMA16816(c[nj], a, bb[nj >> 1][(nj & 1) * 2], bb[nj >> 1][(nj & 1) * 2 + 1]);
    }

    // epilogue
    #pragma unroll
    for (int r = 0; r < 2; r++) {
        int token = m0 + wm + g + r * 8;
        int b = token >> 9, tk = token & 511;
        #pragma unroll
        for (int nj = 0; nj < 8; nj++) {
            int col = n0blk + wn + nj * 8 + tg * 2;
            int h = col >> 5, dk = col & 31;
            float v0 = c[nj][r * 2 + 0] + bias[col];
            float v1 = c[nj][r * 2 + 1] + bias[col + 1];
            int bh = b * NH + h;
            if (z == 0) {
                *(__half2*)&g_Qh[((size_t)(bh * ND + tk)) * DK + dk] =
                    __floats2half2_rn(v0, v1);
            } else if (z == 1) {
                *(__half2*)&g_Kh[((size_t)(bh * NT + tk)) * DK + dk] =
                    __floats2half2_rn(v0, v1);
            } else {
                g_Vht[((size_t)(bh * DK + dk)) * NT + tk]     = __float2half_rn(v0);
                g_Vht[((size_t)(bh * DK + dk + 1)) * NT + tk] = __float2half_rn(v1);
            }
        }
    }
}

// ============================================================
// Tensor-core flash attention: block = (q-tile 64, h, b), 128 thr
//   scores = Q K^T (fp16 mma, fp32 acc), online softmax in regs,
//   P fragments feed P@V mma directly (C-frag == A-frag layout).
// ============================================================
#define QLD 40    // halves; 80B row stride (16B-aligned)
#define VLD 72    // halves; 144B row stride

__global__ void __launch_bounds__(128) attn_tc()
{
    __shared__ __half Qs[64 * QLD];
    __shared__ __half Ks[64 * QLD];
    __shared__ __half Vt[32 * VLD];

    int bh = blockIdx.z * NH + blockIdx.y;
    int q0 = blockIdx.x * 64;
    int h  = blockIdx.y;
    int tid = threadIdx.x;
    int warp = tid >> 5, lane = tid & 31;
    int tg = lane & 3, g = lane >> 2;

    // stage Q [64 q][32 dk]
    #pragma unroll
    for (int i = 0; i < 2; i++) {
        int idx = tid + i * 128;          // 256 uint4
        int row = idx >> 2, part = idx & 3;
        *(uint4*)(Qs + row * QLD + part * 8) =
            *(const uint4*)(g_Qh + ((size_t)(bh * ND + q0 + row)) * DK + part * 8);
    }
    // stage K chunk 0, V^T chunk 0
    #pragma unroll
    for (int i = 0; i < 2; i++) {
        int idx = tid + i * 128;
        int row = idx >> 2, part = idx & 3;
        *(uint4*)(Ks + row * QLD + part * 8) =
            *(const uint4*)(g_Kh + ((size_t)(bh * NT + row)) * DK + part * 8);
    }
    #pragma unroll
    for (int i = 0; i < 2; i++) {
        int idx = tid + i * 128;          // 256 uint4: 32 rows x 8
        int row = idx >> 3, part = idx & 7;
        *(uint4*)(Vt + row * VLD + part * 8) =
            *(const uint4*)(g_Vht + ((size_t)(bh * DK + row)) * NT + part * 8);
    }
    __syncthreads();

    uint32_t aq_base = sm_u32(Qs) +
        (((warp * 16 + (lane & 15)) * QLD + (lane >> 4) * 8) << 1);
    uint32_t bk_base = sm_u32(Ks) +
        (((((lane >> 4) << 3) + (lane & 7)) * QLD + ((lane >> 3) & 1) * 8) << 1);
    uint32_t bv_base = sm_u32(Vt) +
        (((((lane >> 4) << 3) + (lane & 7)) * VLD + ((lane >> 3) & 1) * 8) << 1);

    uint32_t aQ[2][4];
    LDSM_X4(aQ[0], aq_base);
    LDSM_X4(aQ[1], aq_base + 32);

    const float scale = 0.17677669529663689f;  // 1/sqrt(32)
    float m0r = -1e30f, m1r = -1e30f, l0 = 0.f, l1 = 0.f;
    float c2[4][4];
    #pragma unroll
    for (int nt = 0; nt < 4; nt++)
        #pragma unroll
        for (int k = 0; k < 4; k++) c2[nt][k] = 0.f;

    for (int ch = 0; ch < 8; ch++) {
        // ---- scores S[16,64] per warp ----
        float c[8][4];
        #pragma unroll
        for (int nj = 0; nj < 8; nj++)
            #pragma unroll
            for (int k = 0; k < 4; k++) c[nj][k] = 0.f;
        #pragma unroll
        for (int kt = 0; kt < 2; kt++) {
            uint32_t bb[4][4];
            #pragma unroll
            for (int p = 0; p < 4; p++)
                LDSM_X4(bb[p], bk_base + p * 16 * QLD * 2 + kt * 32);
            #pragma unroll
            for (int nj = 0; nj < 8; nj++)
                MMA16816(c[nj], aQ[kt],
                         bb[nj >> 1][(nj & 1) * 2], bb[nj >> 1][(nj & 1) * 2 + 1]);
        }

        // ---- online softmax ----
        float mx0 = -1e30f, mx1 = -1e30f;
        #pragma unroll
        for (int nj = 0; nj < 8; nj++) {
            c[nj][0] *= scale; c[nj][1] *= scale;
            c[nj][2] *= scale; c[nj][3] *= scale;
            mx0 = fmaxf(mx0, fmaxf(c[nj][0], c[nj][1]));
            mx1 = fmaxf(mx1, fmaxf(c[nj][2], c[nj][3]));
        }
        mx0 = fmaxf(mx0, __shfl_xor_sync(0xffffffffu, mx0, 1));
        mx0 = fmaxf(mx0, __shfl_xor_sync(0xffffffffu, mx0, 2));
        mx1 = fmaxf(mx1, __shfl_xor_sync(0xffffffffu, mx1, 1));
        mx1 = fmaxf(mx1, __shfl_xor_sync(0xffffffffu, mx1, 2));
        float mn0 = fmaxf(m0r, mx0), mn1 = fmaxf(m1r, mx1);
        float f0 = __expf(m0r - mn0), f1 = __expf(m1r - mn1);
        m0r = mn0; m1r = mn1;

        float s0 = 0.f, s1 = 0.f;
        uint32_t af[4][4];
        #pragma unroll
        for (int nj = 0; nj < 8; nj++) {
            float p0 = __expf(c[nj][0] - mn0);
            float p1 = __expf(c[nj][1] - mn0);
            float p2 = __expf(c[nj][2] - mn1);
            float p3 = __expf(c[nj][3] - mn1);
            s0 += p0 + p1; s1 += p2 + p3;
            int kt = nj >> 1, half = (nj & 1) * 2;
            af[kt][half]     = f2h2(p0, p1);
            af[kt][half + 1] = f2h2(p2, p3);
        }
        s0 += __shfl_xor_sync(0xffffffffu, s0, 1);
        s0 += __shfl_xor_sync(0xffffffffu, s0, 2);
        s1 += __shfl_xor_sync(0xffffffffu, s1, 1);
        s1 += __shfl_xor_sync(0xffffffffu, s1, 2);
        l0 = l0 * f0 + s0; l1 = l1 * f1 + s1;
        #pragma unroll
        for (int nt = 0; nt < 4; nt++) {
            c2[nt][0] *= f0; c2[nt][1] *= f0;
            c2[nt][2] *= f1; c2[nt][3] *= f1;
        }

        // ---- P @ V ----
        #pragma unroll
        for (int kt = 0; kt < 4; kt++) {
            uint32_t bb[2][4];
            #pragma unroll
            for (int p = 0; p < 2; p++)
                LDSM_X4(bb[p], bv_base + p * 16 * VLD * 2 + kt * 32);
            #pragma unroll
            for (int nt = 0; nt < 4; nt++)
                MMA16816(c2[nt], af[kt],
                         bb[nt >> 1][(nt & 1) * 2], bb[nt >> 1][(nt & 1) * 2 + 1]);
        }

        // ---- stage next chunk ----
        if (ch < 7) {
            __syncthreads();
            int t0 = (ch + 1) * 64;
            #pragma unroll
            for (int i = 0; i < 2; i++) {
                int idx = tid + i * 128;
                int row = idx >> 2, part = idx & 3;
                *(uint4*)(Ks + row * QLD + part * 8) =
                    *(const uint4*)(g_Kh + ((size_t)(bh * NT + t0 + row)) * DK + part * 8);
            }
            #pragma unroll
            for (int i = 0; i < 2; i++) {
                int idx = tid + i * 128;
                int row = idx >> 3, part = idx & 7;
                *(uint4*)(Vt + row * VLD + part * 8) =
                    *(const uint4*)(g_Vht + ((size_t)(bh * DK + row)) * NT + t0 + part * 8);
            }
            __syncthreads();
        }
    }

    // ---- epilogue: ctx / l -> g_ctxh fp16 ----
    float inv0 = 1.f / l0, inv1 = 1.f / l1;
    int token = q0 + warp * 16 + g;
    #pragma unroll
    for (int nt = 0; nt < 4; nt++) {
        int col = h * DK + nt * 8 + tg * 2;
        size_t base_b = (size_t)(blockIdx.z * ND);
        *(__half2*)&g_ctxh[(base_b + token) * DM + col] =
            __floats2half2_rn(c2[nt][0] * inv0, c2[nt][1] * inv0);
        *(__half2*)&g_ctxh[(base_b + token + 8) * DM + col] =
            __floats2half2_rn(c2[nt][2] * inv1, c2[nt][3] * inv1);
    }
}

// ============================================================
// output projection (fp16 mma): attout = ctxh @ w_o^T + b_o (fp32 out)
// ============================================================
__global__ void __launch_bounds__(256)
gemm_o_tc(const float* __restrict__ b_o)
{
    extern __shared__ __align__(16) char dyn[];
    __half* As = (__half*)dyn;
    __half* Bs = (__half*)(dyn + 64 * PALD * 2);

    int tid = threadIdx.x;
    int warp = tid >> 5, lane = tid & 31;
    int m0 = blockIdx.x * 64, n0blk = blockIdx.y * 128;
    int wm = (warp & 3) * 16, wn = (warp >> 2) * 64;
    int tg = lane & 3, g = lane >> 2;

    #pragma unroll
    for (int i = 0; i < 8; i++) {
        int idx = tid + i * 256;
        int row = idx >> 5, kg = idx & 31;
        *(uint4*)(As + row * PALD + kg * 8) =
            *(const uint4*)(g_ctxh + (size_t)(m0 + row) * 256 + kg * 8);
    }
    #pragma unroll
    for (int i = 0; i < 16; i++) {
        int idx = tid + i * 256;
        int row = idx >> 5, kg = idx & 31;
        *(uint4*)(Bs + row * PALD + kg * 8) =
            *(const uint4*)(g_woh + (size_t)(n0blk + row) * 256 + kg * 8);
    }
    __syncthreads();

    uint32_t a_base = sm_u32(As) + (((wm + (lane & 15)) * PALD + (lane >> 4) * 8) << 1);
    uint32_t b_base = sm_u32(Bs) +
        (((wn + ((lane >> 4) << 3) + (lane & 7)) * PALD + ((lane >> 3) & 1) * 8) << 1);

    float c[8][4];
    #pragma unroll
    for (int nj = 0; nj < 8; nj++)
        #pragma unroll
        for (int k = 0; k < 4; k++) c[nj][k] = 0.f;

    #pragma unroll
    for (int kt = 0; kt < 16; kt++) {
        uint32_t a[4];
        LDSM_X4(a, a_base + kt * 32);
        uint32_t bb[4][4];
        #pragma unroll
        for (int p = 0; p < 4; p++)
            LDSM_X4(bb[p], b_base + p * 16 * PALD * 2 + kt * 32);
        #pragma unroll
        for (int nj = 0; nj < 8; nj++)
            MMA16816(c[nj], a, bb[nj >> 1][(nj & 1) * 2], bb[nj >> 1][(nj & 1) * 2 + 1]);
    }

    #pragma unroll
    for (int r = 0; r < 2; r++) {
        int token = m0 + wm + g + r * 8;
        #pragma unroll
        for (int nj = 0; nj < 8; nj++) {
            int col = n0blk + wn + nj * 8 + tg * 2;
            float2 v;
            v.x = c[nj][r * 2 + 0] + b_o[col];
            v.y = c[nj][r * 2 + 1] + b_o[col + 1];
            *(float2*)&g_attout[(size_t)token * 256 + col] = v;
        }
    }
}

// ============================================================
// residual + LayerNorm (emits fp32 + fp16 xn)
// ============================================================
__global__ void ln_kernel(const float* __restrict__ det,
                          const float* __restrict__ ln_g,
                          const float* __restrict__ ln_b)
{
    int row = blockIdx.x, t = threadIdx.x;
    float x = det[row * 256 + t] + g_attout[row * 256 + t];
    float s1 = x, s2 = x * x;
    #pragma unroll
    for (int o = 16; o; o >>= 1) {
        s1 += __shfl_xor_sync(0xffffffffu, s1, o);
        s2 += __shfl_xor_sync(0xffffffffu, s2, o);
    }
    __shared__ float r1[8], r2[8];
    int w = t >> 5, l = t & 31;
    if (!l) { r1[w] = s1; r2[w] = s2; }
    __syncthreads();
    if (w == 0) {
        float a = (l < 8) ? r1[l] : 0.f;
        float c = (l < 8) ? r2[l] : 0.f;
        #pragma unroll
        for (int o = 4; o; o >>= 1) {
            a += __shfl_xor_sync(0xffffffffu, a, o);
            c += __shfl_xor_sync(0xffffffffu, c, o);
        }
        if (!l) { r1[0] = a; r2[0] = c; }
    }
    __syncthreads();
    float mu  = r1[0] * (1.f / 256.f);
    float var = r2[0] * (1.f / 256.f) - mu * mu;
    float xn = (x - mu) * rsqrtf(var + 1e-5f) * ln_g[t] + ln_b[t];
    g_xn[row * 256 + t] = xn;
    g_xnh[row * 256 + t] = __float2half_rn(xn);
}

// ============================================================
// Pairwise MLP (verified round-7 version)
// ============================================================
#define NPER 8
#define ALDH 264
#define BLDH 264
#define MLP_DYN (128 * ALDH * 2 + 128 * BLDH * 2)   // 135168

__global__ void __launch_bounds__(256, 1)
mlp_mma(const float* __restrict__ b1,
        const float* __restrict__ w2,
        const float* __restrict__ b2,
        float* __restrict__ out)
{
    extern __shared__ __align__(16) char dyn[];
    __half* As = (__half*)dyn;                     // [128][ALDH]
    __half* Bs = (__half*)(dyn + 128 * ALDH * 2);  // [128][BLDH]
    __shared__ float b1s[128], w2s[128], psum[128];

    int b  = blockIdx.z;
    int t0 = blockIdx.x * 128;
    int n0 = blockIdx.y * NPER;
    int tid = threadIdx.x;
    int warp = tid >> 5, lane = tid & 31;
    int wt = (warp & 3) * 32;
    int wh = (warp >> 2) * 64;
    int tg = lane & 3, g = lane >> 2;

    if (tid < 128) { b1s[tid] = b1[tid]; w2s[tid] = w2[tid]; }
    float bias2 = b2[0];

    const __half* trkh = g_trkh + ((size_t)(b * NT + t0)) * 256;
    #pragma unroll
    for (int i = 0; i < 16; i++) {
        int idx = tid + i * 256;
        int row = idx >> 5, kg = idx & 31;
        *(uint4*)(As + row * ALDH + kg * 8) =
            *(const uint4*)(trkh + row * 256 + kg * 8);
    }

    uint32_t a_base = sm_u32(As) +
        (((wt + (lane & 15)) * ALDH + (lane >> 4) * 8) << 1);
    uint32_t b_base = sm_u32(Bs) +
        (((wh + ((lane >> 4) << 3) + (lane & 7)) * BLDH + ((lane >> 3) & 1) * 8) << 1);

    for (int ni = 0; ni < NPER; ni++) {
        int n = n0 + ni;

        const __half* xh = g_xnh + ((size_t)(b * ND + n)) * 256;
        #pragma unroll
        for (int i = 0; i < 16; i++) {
            int idx = tid + i * 256;
            int hrow = idx >> 5, kg = idx & 31;
            uint4 wv = *(const uint4*)(g_w1h + hrow * 256 + kg * 8);
            uint4 xv = *(const uint4*)(xh + kg * 8);
            __half2* wp = (__half2*)&wv;
            const __half2* xp = (const __half2*)&xv;
            wp[0] = __hmul2(wp[0], xp[0]); wp[1] = __hmul2(wp[1], xp[1]);
            wp[2] = __hmul2(wp[2], xp[2]); wp[3] = __hmul2(wp[3], xp[3]);
            *(uint4*)(Bs + hrow * BLDH + kg * 8) = wv;
        }
        __syncthreads();

        float c[2][8][4];
        #pragma unroll
        for (int mi = 0; mi < 2; mi++)
            #pragma unroll
            for (int nj = 0; nj < 8; nj++)
                #pragma unroll
                for (int k = 0; k < 4; k++) c[mi][nj][k] = 0.f;

        #pragma unroll
        for (int kk = 0; kk < 16; kk++) {
            uint32_t a[2][4];
            LDSM_X4(a[0], a_base + kk * 32);
            LDSM_X4(a[1], a_base + 16 * ALDH * 2 + kk * 32);
            uint32_t bb[4][4];
            #pragma unroll
            for (int p = 0; p < 4; p++)
                LDSM_X4(bb[p], b_base + p * 16 * BLDH * 2 + kk * 32);
            #pragma unroll
            for (int mi = 0; mi < 2; mi++)
                #pragma unroll
                for (int nj = 0; nj < 8; nj++)
                    MMA16816(c[mi][nj], a[mi],
                             bb[nj >> 1][(nj & 1) * 2], bb[nj >> 1][(nj & 1) * 2 + 1]);
        }

        float sreg[2][2];
        #pragma unroll
        for (int mi = 0; mi < 2; mi++) {
            float s0 = 0.f, s1 = 0.f;
            #pragma unroll
            for (int nj = 0; nj < 8; nj++) {
                int col0 = wh + nj * 8 + tg * 2;
                float bb0 = b1s[col0], ww0 = w2s[col0];
                float bb1 = b1s[col0 + 1], ww1 = w2s[col0 + 1];
                s0 += fmaxf(c[mi][nj][0] + bb0, 0.f) * ww0
                    + fmaxf(c[mi][nj][1] + bb1, 0.f) * ww1;
                s1 += fmaxf(c[mi][nj][2] + bb0, 0.f) * ww0
                    + fmaxf(c[mi][nj][3] + bb1, 0.f) * ww1;
            }
            s0 += __shfl_xor_sync(0xffffffffu, s0, 1);
            s0 += __shfl_xor_sync(0xffffffffu, s0, 2);
            s1 += __shfl_xor_sync(0xffffffffu, s1, 1);
            s1 += __shfl_xor_sync(0xffffffffu, s1, 2);
            sreg[mi][0] = s0; sreg[mi][1] = s1;
            if (warp >= 4 && tg == 0) {
                psum[wt + mi * 16 + g]     = s0;
                psum[wt + mi * 16 + g + 8] = s1;
            }
        }
        __syncthreads();
        if (warp < 4 && tg == 0) {
            #pragma unroll
            for (int mi = 0; mi < 2; mi++) {
                int t = wt + mi * 16 + g;
                float l0 = sreg[mi][0] + psum[t]     + bias2;
                float l1 = sreg[mi][1] + psum[t + 8] + bias2;
                size_t base = ((size_t)(b * ND + n)) * NT + t0;
                out[base + t]     = 1.f / (1.f + __expf(-l0));
                out[base + t + 8] = 1.f / (1.f + __expf(-l1));
            }
        }
    }
}

// ============================================================
extern "C" void kernel_launch(void* const* d_in, const int* in_sizes, int n_in,
                              void* d_out, int out_size)
{
    const float* det  = (const float*)d_in[0];
    const float* trk  = (const float*)d_in[1];
    const float* w_q  = (const float*)d_in[2];
    const float* b_q  = (const float*)d_in[3];
    const float* w_k  = (const float*)d_in[4];
    const float* b_k  = (const float*)d_in[5];
    const float* w_v  = (const float*)d_in[6];
    const float* b_v  = (const float*)d_in[7];
    const float* w_o  = (const float*)d_in[8];
    const float* b_o  = (const float*)d_in[9];
    const float* ln_g = (const float*)d_in[10];
    const float* ln_b = (const float*)d_in[11];
    const float* w1   = (const float*)d_in[12];
    const float* b1   = (const float*)d_in[13];
    const float* w2   = (const float*)d_in[14];
    const float* b2   = (const float*)d_in[15];
    float* out = (float*)d_out;

    cudaFuncSetAttribute(mlp_mma,
                         cudaFuncAttributeMaxDynamicSharedMemorySize, MLP_DYN);
    cudaFuncSetAttribute(proj_gemm,
                         cudaFuncAttributeMaxDynamicSharedMemorySize, PROJ_SMEM);
    cudaFuncSetAttribute(gemm_o_tc,
                         cudaFuncAttributeMaxDynamicSharedMemorySize, PROJ_SMEM);

    prep_half<<<2048, 256>>>(det, trk, w_q, w_k, w_v, w_o, w1);
    proj_gemm<<<dim3(32, 2, 3), 256, PROJ_SMEM>>>(b_q, b_k, b_v);
    attn_tc<<<dim3(8, NH, BB), 128>>>();
    gemm_o_tc<<<dim3(32, 2), 256, PROJ_SMEM>>>(b_o);
    ln_kernel<<<BB * ND, 256>>>(det, ln_g, ln_b);
    mlp_mma<<<dim3(4, ND / NPER, BB), 256, MLP_DYN>>>(b1, w2, b2, out);
}

// round 9
// speedup vs baseline: 7.3556x; 1.1129x over previous
#include <cuda_runtime.h>
#include <cuda_fp16.h>
#include <math.h>
#include <stdint.h>

#define BB 4
#define ND 512
#define NT 512
#define DM 256
#define NH 8
#define DK 32

// ---- scratch (static device globals; no runtime allocation) ----
__device__ __half g_deth[BB*ND*DM];       // detections fp16
__device__ __half g_trkh[BB*NT*DM];       // tracks fp16
__device__ __half g_wqh[DM*DM], g_wkh[DM*DM], g_wvh[DM*DM], g_woh[DM*DM];
__device__ __half g_w1h[128*DM];
__device__ __half g_Qh[BB*NH*ND*DK];      // [bh][q][dk]
__device__ __half g_Kh[BB*NH*NT*DK];      // [bh][t][dk]
__device__ __half g_Vht[BB*NH*DK*NT];     // [bh][dk][t]  (transposed)
__device__ __half g_ctxh[BB*ND*DM];       // attention output fp16 [token][256]
__device__ float g_attout[BB*ND*DM];      // attended (pre-residual)
__device__ float g_xn[BB*ND*DM];          // LayerNorm output (fp32)
__device__ __half g_xnh[BB*ND*DM];        // LayerNorm output (fp16)

static __device__ __forceinline__ uint32_t sm_u32(const void* p) {
    uint32_t a;
    asm("{ .reg .u64 t; cvta.to.shared.u64 t, %1; cvt.u32.u64 %0, t; }"
        : "=r"(a) : "l"(p));
    return a;
}
static __device__ __forceinline__ uint32_t f2h2(float a, float b) {
    __half2 h = __floats2half2_rn(a, b);
    return *reinterpret_cast<uint32_t*>(&h);
}

#define LDSM_X4(r, addr) \
    asm volatile("ldmatrix.sync.aligned.m8n8.x4.shared.b16 {%0,%1,%2,%3}, [%4];" \
        : "=r"((r)[0]), "=r"((r)[1]), "=r"((r)[2]), "=r"((r)[3]) : "r"(addr))
#define MMA16816(c, a, b0, b1) \
    asm volatile("mma.sync.aligned.m16n8k16.row.col.f32.f16.f16.f32 " \
        "{%0,%1,%2,%3}, {%4,%5,%6,%7}, {%8,%9}, {%0,%1,%2,%3};" \
        : "+f"((c)[0]), "+f"((c)[1]), "+f"((c)[2]), "+f"((c)[3]) \
        : "r"((a)[0]), "r"((a)[1]), "r"((a)[2]), "r"((a)[3]), "r"(b0), "r"(b1))

// ============================================================
// prep: fp32 -> fp16 copies
// ============================================================
__global__ void prep_half(const float* __restrict__ det,
                          const float* __restrict__ trk,
                          const float* __restrict__ w_q, const float* __restrict__ w_k,
                          const float* __restrict__ w_v, const float* __restrict__ w_o,
                          const float* __restrict__ w1)
{
    int idx = blockIdx.x * 256 + threadIdx.x;   // 0 .. 524287
    g_deth[idx] = __float2half_rn(det[idx]);
    g_trkh[idx] = __float2half_rn(trk[idx]);
    if (idx < DM * DM) {
        g_wqh[idx] = __float2half_rn(w_q[idx]);
        g_wkh[idx] = __float2half_rn(w_k[idx]);
        g_wvh[idx] = __float2half_rn(w_v[idx]);
        g_woh[idx] = __float2half_rn(w_o[idx]);
    }
    if (idx < 128 * DM) g_w1h[idx] = __float2half_rn(w1[idx]);
}

// ============================================================
// Projection GEMM (fp16 mma): C[2048,256] = X @ W^T + bias
//   z = 0: Q -> g_Qh;  z = 1: K -> g_Kh;  z = 2: V -> g_Vht (transposed)
// ============================================================
#define PALD 264
#define PROJ_SMEM ((64 * PALD + 128 * PALD) * 2)   // 101376

__global__ void __launch_bounds__(256)
proj_gemm(const float* __restrict__ b_q, const float* __restrict__ b_k,
          const float* __restrict__ b_v)
{
    int z = blockIdx.z;
    const __half* X = (z == 0) ? g_deth : g_trkh;
    const __half* W = (z == 0) ? g_wqh : (z == 1) ? g_wkh : g_wvh;
    const float* bias = (z == 0) ? b_q : (z == 1) ? b_k : b_v;

    extern __shared__ __align__(16) char dyn[];
    __half* As = (__half*)dyn;                      // [64][PALD]
    __half* Bs = (__half*)(dyn + 64 * PALD * 2);    // [128][PALD]

    int tid = threadIdx.x;
    int warp = tid >> 5, lane = tid & 31;
    int m0 = blockIdx.x * 64, n0blk = blockIdx.y * 128;
    int wm = (warp & 3) * 16, wn = (warp >> 2) * 64;
    int tg = lane & 3, g = lane >> 2;

    #pragma unroll
    for (int i = 0; i < 8; i++) {
        int idx = tid + i * 256;
        int row = idx >> 5, kg = idx & 31;
        *(uint4*)(As + row * PALD + kg * 8) =
            *(const uint4*)(X + (size_t)(m0 + row) * 256 + kg * 8);
    }
    #pragma unroll
    for (int i = 0; i < 16; i++) {
        int idx = tid + i * 256;
        int row = idx >> 5, kg = idx & 31;
        *(uint4*)(Bs + row * PALD + kg * 8) =
            *(const uint4*)(W + (size_t)(n0blk + row) * 256 + kg * 8);
    }
    __syncthreads();

    uint32_t a_base = sm_u32(As) + (((wm + (lane & 15)) * PALD + (lane >> 4) * 8) << 1);
    uint32_t b_base = sm_u32(Bs) +
        (((wn + ((lane >> 4) << 3) + (lane & 7)) * PALD + ((lane >> 3) & 1) * 8) << 1);

    float c[8][4];
    #pragma unroll
    for (int nj = 0; nj < 8; nj++)
        #pragma unroll
        for (int k = 0; k < 4; k++) c[nj][k] = 0.f;

    #pragma unroll
    for (int kt = 0; kt < 16; kt++) {
        uint32_t a[4];
        LDSM_X4(a, a_base + kt * 32);
        uint32_t bb[4][4];
        #pragma unroll
        for (int p = 0; p < 4; p++)
            LDSM_X4(bb[p], b_base + p * 16 * PALD * 2 + kt * 32);
        #pragma unroll
        for (int nj = 0; nj < 8; nj++)
            MMA16816(c[nj], a, bb[nj >> 1][(nj & 1) * 2], bb[nj >> 1][(nj & 1) * 2 + 1]);
    }

    #pragma unroll
    for (int r = 0; r < 2; r++) {
        int token = m0 + wm + g + r * 8;
        int b = token >> 9, tk = token & 511;
        #pragma unroll
        for (int nj = 0; nj < 8; nj++) {
            int col = n0blk + wn + nj * 8 + tg * 2;
            int h = col >> 5, dk = col & 31;
            float v0 = c[nj][r * 2 + 0] + bias[col];
            float v1 = c[nj][r * 2 + 1] + bias[col + 1];
            int bh = b * NH + h;
            if (z == 0) {
                *(__half2*)&g_Qh[((size_t)(bh * ND + tk)) * DK + dk] =
                    __floats2half2_rn(v0, v1);
            } else if (z == 1) {
                *(__half2*)&g_Kh[((size_t)(bh * NT + tk)) * DK + dk] =
                    __floats2half2_rn(v0, v1);
            } else {
                g_Vht[((size_t)(bh * DK + dk)) * NT + tk]     = __float2half_rn(v0);
                g_Vht[((size_t)(bh * DK + dk + 1)) * NT + tk] = __float2half_rn(v1);
            }
        }
    }
}

// ============================================================
// Tensor-core flash attention (verified round-8 version)
// ============================================================
#define QLD 40
#define VLD 72

__global__ void __launch_bounds__(128) attn_tc()
{
    __shared__ __half Qs[64 * QLD];
    __shared__ __half Ks[64 * QLD];
    __shared__ __half Vt[32 * VLD];

    int bh = blockIdx.z * NH + blockIdx.y;
    int q0 = blockIdx.x * 64;
    int h  = blockIdx.y;
    int tid = threadIdx.x;
    int warp = tid >> 5, lane = tid & 31;
    int tg = lane & 3, g = lane >> 2;

    #pragma unroll
    for (int i = 0; i < 2; i++) {
        int idx = tid + i * 128;
        int row = idx >> 2, part = idx & 3;
        *(uint4*)(Qs + row * QLD + part * 8) =
            *(const uint4*)(g_Qh + ((size_t)(bh * ND + q0 + row)) * DK + part * 8);
    }
    #pragma unroll
    for (int i = 0; i < 2; i++) {
        int idx = tid + i * 128;
        int row = idx >> 2, part = idx & 3;
        *(uint4*)(Ks + row * QLD + part * 8) =
            *(const uint4*)(g_Kh + ((size_t)(bh * NT + row)) * DK + part * 8);
    }
    #pragma unroll
    for (int i = 0; i < 2; i++) {
        int idx = tid + i * 128;
        int row = idx >> 3, part = idx & 7;
        *(uint4*)(Vt + row * VLD + part * 8) =
            *(const uint4*)(g_Vht + ((size_t)(bh * DK + row)) * NT + part * 8);
    }
    __syncthreads();

    uint32_t aq_base = sm_u32(Qs) +
        (((warp * 16 + (lane & 15)) * QLD + (lane >> 4) * 8) << 1);
    uint32_t bk_base = sm_u32(Ks) +
        (((((lane >> 4) << 3) + (lane & 7)) * QLD + ((lane >> 3) & 1) * 8) << 1);
    uint32_t bv_base = sm_u32(Vt) +
        (((((lane >> 4) << 3) + (lane & 7)) * VLD + ((lane >> 3) & 1) * 8) << 1);

    uint32_t aQ[2][4];
    LDSM_X4(aQ[0], aq_base);
    LDSM_X4(aQ[1], aq_base + 32);

    const float scale = 0.17677669529663689f;
    float m0r = -1e30f, m1r = -1e30f, l0 = 0.f, l1 = 0.f;
    float c2[4][4];
    #pragma unroll
    for (int nt = 0; nt < 4; nt++)
        #pragma unroll
        for (int k = 0; k < 4; k++) c2[nt][k] = 0.f;

    for (int ch = 0; ch < 8; ch++) {
        float c[8][4];
        #pragma unroll
        for (int nj = 0; nj < 8; nj++)
            #pragma unroll
            for (int k = 0; k < 4; k++) c[nj][k] = 0.f;
        #pragma unroll
        for (int kt = 0; kt < 2; kt++) {
            uint32_t bb[4][4];
            #pragma unroll
            for (int p = 0; p < 4; p++)
                LDSM_X4(bb[p], bk_base + p * 16 * QLD * 2 + kt * 32);
            #pragma unroll
            for (int nj = 0; nj < 8; nj++)
                MMA16816(c[nj], aQ[kt],
                         bb[nj >> 1][(nj & 1) * 2], bb[nj >> 1][(nj & 1) * 2 + 1]);
        }

        float mx0 = -1e30f, mx1 = -1e30f;
        #pragma unroll
        for (int nj = 0; nj < 8; nj++) {
            c[nj][0] *= scale; c[nj][1] *= scale;
            c[nj][2] *= scale; c[nj][3] *= scale;
            mx0 = fmaxf(mx0, fmaxf(c[nj][0], c[nj][1]));
            mx1 = fmaxf(mx1, fmaxf(c[nj][2], c[nj][3]));
        }
        mx0 = fmaxf(mx0, __shfl_xor_sync(0xffffffffu, mx0, 1));
        mx0 = fmaxf(mx0, __shfl_xor_sync(0xffffffffu, mx0, 2));
        mx1 = fmaxf(mx1, __shfl_xor_sync(0xffffffffu, mx1, 1));
        mx1 = fmaxf(mx1, __shfl_xor_sync(0xffffffffu, mx1, 2));
        float mn0 = fmaxf(m0r, mx0), mn1 = fmaxf(m1r, mx1);
        float f0 = __expf(m0r - mn0), f1 = __expf(m1r - mn1);
        m0r = mn0; m1r = mn1;

        float s0 = 0.f, s1 = 0.f;
        uint32_t af[4][4];
        #pragma unroll
        for (int nj = 0; nj < 8; nj++) {
            float p0 = __expf(c[nj][0] - mn0);
            float p1 = __expf(c[nj][1] - mn0);
            float p2 = __expf(c[nj][2] - mn1);
            float p3 = __expf(c[nj][3] - mn1);
            s0 += p0 + p1; s1 += p2 + p3;
            int kt = nj >> 1, half = (nj & 1) * 2;
            af[kt][half]     = f2h2(p0, p1);
            af[kt][half + 1] = f2h2(p2, p3);
        }
        s0 += __shfl_xor_sync(0xffffffffu, s0, 1);
        s0 += __shfl_xor_sync(0xffffffffu, s0, 2);
        s1 += __shfl_xor_sync(0xffffffffu, s1, 1);
        s1 += __shfl_xor_sync(0xffffffffu, s1, 2);
        l0 = l0 * f0 + s0; l1 = l1 * f1 + s1;
        #pragma unroll
        for (int nt = 0; nt < 4; nt++) {
            c2[nt][0] *= f0; c2[nt][1] *= f0;
            c2[nt][2] *= f1; c2[nt][3] *= f1;
        }

        #pragma unroll
        for (int kt = 0; kt < 4; kt++) {
            uint32_t bb[2][4];
            #pragma unroll
            for (int p = 0; p < 2; p++)
                LDSM_X4(bb[p], bv_base + p * 16 * VLD * 2 + kt * 32);
            #pragma unroll
            for (int nt = 0; nt < 4; nt++)
                MMA16816(c2[nt], af[kt],
                         bb[nt >> 1][(nt & 1) * 2], bb[nt >> 1][(nt & 1) * 2 + 1]);
        }

        if (ch < 7) {
            __syncthreads();
            int t0 = (ch + 1) * 64;
            #pragma unroll
            for (int i = 0; i < 2; i++) {
                int idx = tid + i * 128;
                int row = idx >> 2, part = idx & 3;
                *(uint4*)(Ks + row * QLD + part * 8) =
                    *(const uint4*)(g_Kh + ((size_t)(bh * NT + t0 + row)) * DK + part * 8);
            }
            #pragma unroll
            for (int i = 0; i < 2; i++) {
                int idx = tid + i * 128;
                int row = idx >> 3, part = idx & 7;
                *(uint4*)(Vt + row * VLD + part * 8) =
                    *(const uint4*)(g_Vht + ((size_t)(bh * DK + row)) * NT + t0 + part * 8);
            }
            __syncthreads();
        }
    }

    float inv0 = 1.f / l0, inv1 = 1.f / l1;
    int token = q0 + warp * 16 + g;
    #pragma unroll
    for (int nt = 0; nt < 4; nt++) {
        int col = h * DK + nt * 8 + tg * 2;
        size_t base_b = (size_t)(blockIdx.z * ND);
        *(__half2*)&g_ctxh[(base_b + token) * DM + col] =
            __floats2half2_rn(c2[nt][0] * inv0, c2[nt][1] * inv0);
        *(__half2*)&g_ctxh[(base_b + token + 8) * DM + col] =
            __floats2half2_rn(c2[nt][2] * inv1, c2[nt][3] * inv1);
    }
}

// ============================================================
// output projection (fp16 mma): attout = ctxh @ w_o^T + b_o (fp32 out)
// ============================================================
__global__ void __launch_bounds__(256)
gemm_o_tc(const float* __restrict__ b_o)
{
    extern __shared__ __align__(16) char dyn[];
    __half* As = (__half*)dyn;
    __half* Bs = (__half*)(dyn + 64 * PALD * 2);

    int tid = threadIdx.x;
    int warp = tid >> 5, lane = tid & 31;
    int m0 = blockIdx.x * 64, n0blk = blockIdx.y * 128;
    int wm = (warp & 3) * 16, wn = (warp >> 2) * 64;
    int tg = lane & 3, g = lane >> 2;

    #pragma unroll
    for (int i = 0; i < 8; i++) {
        int idx = tid + i * 256;
        int row = idx >> 5, kg = idx & 31;
        *(uint4*)(As + row * PALD + kg * 8) =
            *(const uint4*)(g_ctxh + (size_t)(m0 + row) * 256 + kg * 8);
    }
    #pragma unroll
    for (int i = 0; i < 16; i++) {
        int idx = tid + i * 256;
        int row = idx >> 5, kg = idx & 31;
        *(uint4*)(Bs + row * PALD + kg * 8) =
            *(const uint4*)(g_woh + (size_t)(n0blk + row) * 256 + kg * 8);
    }
    __syncthreads();

    uint32_t a_base = sm_u32(As) + (((wm + (lane & 15)) * PALD + (lane >> 4) * 8) << 1);
    uint32_t b_base = sm_u32(Bs) +
        (((wn + ((lane >> 4) << 3) + (lane & 7)) * PALD + ((lane >> 3) & 1) * 8) << 1);

    float c[8][4];
    #pragma unroll
    for (int nj = 0; nj < 8; nj++)
        #pragma unroll
        for (int k = 0; k < 4; k++) c[nj][k] = 0.f;

    #pragma unroll
    for (int kt = 0; kt < 16; kt++) {
        uint32_t a[4];
        LDSM_X4(a, a_base + kt * 32);
        uint32_t bb[4][4];
        #pragma unroll
        for (int p = 0; p < 4; p++)
            LDSM_X4(bb[p], b_base + p * 16 * PALD * 2 + kt * 32);
        #pragma unroll
        for (int nj = 0; nj < 8; nj++)
            MMA16816(c[nj], a, bb[nj >> 1][(nj & 1) * 2], bb[nj >> 1][(nj & 1) * 2 + 1]);
    }

    #pragma unroll
    for (int r = 0; r < 2; r++) {
        int token = m0 + wm + g + r * 8;
        #pragma unroll
        for (int nj = 0; nj < 8; nj++) {
            int col = n0blk + wn + nj * 8 + tg * 2;
            float2 v;
            v.x = c[nj][r * 2 + 0] + b_o[col];
            v.y = c[nj][r * 2 + 1] + b_o[col + 1];
            *(float2*)&g_attout[(size_t)token * 256 + col] = v;
        }
    }
}

// ============================================================
// residual + LayerNorm (emits fp32 + fp16 xn)
// ============================================================
__global__ void ln_kernel(const float* __restrict__ det,
                          const float* __restrict__ ln_g,
                          const float* __restrict__ ln_b)
{
    int row = blockIdx.x, t = threadIdx.x;
    float x = det[row * 256 + t] + g_attout[row * 256 + t];
    float s1 = x, s2 = x * x;
    #pragma unroll
    for (int o = 16; o; o >>= 1) {
        s1 += __shfl_xor_sync(0xffffffffu, s1, o);
        s2 += __shfl_xor_sync(0xffffffffu, s2, o);
    }
    __shared__ float r1[8], r2[8];
    int w = t >> 5, l = t & 31;
    if (!l) { r1[w] = s1; r2[w] = s2; }
    __syncthreads();
    if (w == 0) {
        float a = (l < 8) ? r1[l] : 0.f;
        float c = (l < 8) ? r2[l] : 0.f;
        #pragma unroll
        for (int o = 4; o; o >>= 1) {
            a += __shfl_xor_sync(0xffffffffu, a, o);
            c += __shfl_xor_sync(0xffffffffu, c, o);
        }
        if (!l) { r1[0] = a; r2[0] = c; }
    }
    __syncthreads();
    float mu  = r1[0] * (1.f / 256.f);
    float var = r2[0] * (1.f / 256.f) - mu * mu;
    float xn = (x - mu) * rsqrtf(var + 1e-5f) * ln_g[t] + ln_b[t];
    g_xn[row * 256 + t] = xn;
    g_xnh[row * 256 + t] = __float2half_rn(xn);
}

// ============================================================
// Pairwise MLP v4: tracks AND w1 smem-resident (n-invariant);
// xn applied to A-fragments in registers (8 HMUL2 per k-tile).
// One barrier per n-iter (double-buffered xns/psum).
// ============================================================
#define NPER 8
#define ALDH 264
#define BLDH 264
#define MLP_DYN (128 * ALDH * 2 + 128 * BLDH * 2)   // 135168

__global__ void __launch_bounds__(256, 1)
mlp_mma(const float* __restrict__ b1,
        const float* __restrict__ w2,
        const float* __restrict__ b2,
        float* __restrict__ out)
{
    extern __shared__ __align__(16) char dyn[];
    __half* As = (__half*)dyn;                     // tracks [128][ALDH]
    __half* Bs = (__half*)(dyn + 128 * ALDH * 2);  // w1     [128][BLDH]
    __shared__ float b1s[128], w2s[128];
    __shared__ float psum[2][128];
    __shared__ __half2 xns[2][128];

    int b  = blockIdx.z;
    int t0 = blockIdx.x * 128;
    int n0 = blockIdx.y * NPER;
    int tid = threadIdx.x;
    int warp = tid >> 5, lane = tid & 31;
    int wt = (warp & 3) * 32;
    int wh = (warp >> 2) * 64;
    int tg = lane & 3, g = lane >> 2;

    if (tid < 128) { b1s[tid] = b1[tid]; w2s[tid] = w2[tid]; }
    float bias2 = b2[0];

    // stage tracks (A) once
    const __half* trkh = g_trkh + ((size_t)(b * NT + t0)) * 256;
    #pragma unroll
    for (int i = 0; i < 16; i++) {
        int idx = tid + i * 256;
        int row = idx >> 5, kg = idx & 31;
        *(uint4*)(As + row * ALDH + kg * 8) =
            *(const uint4*)(trkh + row * 256 + kg * 8);
    }
    // stage w1 (B) once
    #pragma unroll
    for (int i = 0; i < 16; i++) {
        int idx = tid + i * 256;
        int row = idx >> 5, kg = idx & 31;
        *(uint4*)(Bs + row * BLDH + kg * 8) =
            *(const uint4*)(g_w1h + row * 256 + kg * 8);
    }
    // stage xn for first n
    if (tid < 128)
        xns[0][tid] = ((const __half2*)(g_xnh + ((size_t)(b * ND + n0)) * 256))[tid];
    __syncthreads();

    uint32_t a_base = sm_u32(As) +
        (((wt + (lane & 15)) * ALDH + (lane >> 4) * 8) << 1);
    uint32_t b_base = sm_u32(Bs) +
        (((wh + ((lane >> 4) << 3) + (lane & 7)) * BLDH + ((lane >> 3) & 1) * 8) << 1);

    for (int ni = 0; ni < NPER; ni++) {
        int n = n0 + ni;
        int par = ni & 1;

        float c[2][8][4];
        #pragma unroll
        for (int mi = 0; mi < 2; mi++)
            #pragma unroll
            for (int nj = 0; nj < 8; nj++)
                #pragma unroll
                for (int k = 0; k < 4; k++) c[mi][nj][k] = 0.f;

        #pragma unroll
        for (int kk = 0; kk < 16; kk++) {
            uint32_t a[2][4];
            LDSM_X4(a[0], a_base + kk * 32);
            LDSM_X4(a[1], a_base + 16 * ALDH * 2 + kk * 32);
            // scale A fragments by xn[k]: a0,a1 <- k=tg*2; a2,a3 <- k=8+tg*2
            __half2 xlo = xns[par][kk * 8 + tg];
            __half2 xhi = xns[par][kk * 8 + 4 + tg];
            #pragma unroll
            for (int mi = 0; mi < 2; mi++) {
                __half2* ap = (__half2*)a[mi];
                ap[0] = __hmul2(ap[0], xlo);
                ap[1] = __hmul2(ap[1], xlo);
                ap[2] = __hmul2(ap[2], xhi);
                ap[3] = __hmul2(ap[3], xhi);
            }
            uint32_t bb[4][4];
            #pragma unroll
            for (int p = 0; p < 4; p++)
                LDSM_X4(bb[p], b_base + p * 16 * BLDH * 2 + kk * 32);
            #pragma unroll
            for (int mi = 0; mi < 2; mi++)
                #pragma unroll
                for (int nj = 0; nj < 8; nj++)
                    MMA16816(c[mi][nj], a[mi],
                             bb[nj >> 1][(nj & 1) * 2], bb[nj >> 1][(nj & 1) * 2 + 1]);
        }

        // prefetch next n's xn (before the barrier)
        if (ni < NPER - 1 && tid < 128)
            xns[par ^ 1][tid] =
                ((const __half2*)(g_xnh + ((size_t)(b * ND + n + 1)) * 256))[tid];

        // register epilogue
        float sreg[2][2];
        #pragma unroll
        for (int mi = 0; mi < 2; mi++) {
            float s0 = 0.f, s1 = 0.f;
            #pragma unroll
            for (int nj = 0; nj < 8; nj++) {
                int col0 = wh + nj * 8 + tg * 2;
                float bb0 = b1s[col0], ww0 = w2s[col0];
                float bb1 = b1s[col0 + 1], ww1 = w2s[col0 + 1];
                s0 += fmaxf(c[mi][nj][0] + bb0, 0.f) * ww0
                    + fmaxf(c[mi][nj][1] + bb1, 0.f) * ww1;
                s1 += fmaxf(c[mi][nj][2] + bb0, 0.f) * ww0
                    + fmaxf(c[mi][nj][3] + bb1, 0.f) * ww1;
            }
            s0 += __shfl_xor_sync(0xffffffffu, s0, 1);
            s0 += __shfl_xor_sync(0xffffffffu, s0, 2);
            s1 += __shfl_xor_sync(0xffffffffu, s1, 1);
            s1 += __shfl_xor_sync(0xffffffffu, s1, 2);
            sreg[mi][0] = s0; sreg[mi][1] = s1;
            if (warp >= 4 && tg == 0) {
                psum[par][wt + mi * 16 + g]     = s0;
                psum[par][wt + mi * 16 + g + 8] = s1;
            }
        }
        __syncthreads();   // psum[par] + xns[par^1] ready
        if (warp < 4 && tg == 0) {
            #pragma unroll
            for (int mi = 0; mi < 2; mi++) {
                int t = wt + mi * 16 + g;
                float l0 = sreg[mi][0] + psum[par][t]     + bias2;
                float l1 = sreg[mi][1] + psum[par][t + 8] + bias2;
                size_t base = ((size_t)(b * ND + n)) * NT + t0;
                out[base + t]     = 1.f / (1.f + __expf(-l0));
                out[base + t + 8] = 1.f / (1.f + __expf(-l1));
            }
        }
    }
}

// ============================================================
extern "C" void kernel_launch(void* const* d_in, const int* in_sizes, int n_in,
                              void* d_out, int out_size)
{
    const float* det  = (const float*)d_in[0];
    const float* trk  = (const float*)d_in[1];
    const float* w_q  = (const float*)d_in[2];
    const float* b_q  = (const float*)d_in[3];
    const float* w_k  = (const float*)d_in[4];
    const float* b_k  = (const float*)d_in[5];
    const float* w_v  = (const float*)d_in[6];
    const float* b_v  = (const float*)d_in[7];
    const float* w_o  = (const float*)d_in[8];
    const float* b_o  = (const float*)d_in[9];
    const float* ln_g = (const float*)d_in[10];
    const float* ln_b = (const float*)d_in[11];
    const float* w1   = (const float*)d_in[12];
    const float* b1   = (const float*)d_in[13];
    const float* w2   = (const float*)d_in[14];
    const float* b2   = (const float*)d_in[15];
    float* out = (float*)d_out;

    cudaFuncSetAttribute(mlp_mma,
                         cudaFuncAttributeMaxDynamicSharedMemorySize, MLP_DYN);
    cudaFuncSetAttribute(proj_gemm,
                         cudaFuncAttributeMaxDynamicSharedMemorySize, PROJ_SMEM);
    cudaFuncSetAttribute(gemm_o_tc,
                         cudaFuncAttributeMaxDynamicSharedMemorySize, PROJ_SMEM);

    prep_half<<<2048, 256>>>(det, trk, w_q, w_k, w_v, w_o, w1);
    proj_gemm<<<dim3(32, 2, 3), 256, PROJ_SMEM>>>(b_q, b_k, b_v);
    attn_tc<<<dim3(8, NH, BB), 128>>>();
    gemm_o_tc<<<dim3(32, 2), 256, PROJ_SMEM>>>(b_o);
    ln_kernel<<<BB * ND, 256>>>(det, ln_g, ln_b);
    mlp_mma<<<dim3(4, ND / NPER, BB), 256, MLP_DYN>>>(b1, w2, b2, out);
}